// round 6
// baseline (speedup 1.0000x reference)
#include <cuda_runtime.h>
#include <cuda_bf16.h>
#include <cuda_fp16.h>
#include <cstdint>

#define N_NODES 50000
#define N_EDGES 1600000
#define DIM 256
#define M_PAD 50048              // 391 * 128
#define BUCKET_CAP 128

// ---- device scratch (no allocations allowed) ----
__device__ __half g_y[(size_t)M_PAD * DIM];         // y = x @ W^T  (fp16, 25.6 MB)
__device__ int      g_count[N_NODES];
__device__ uint32_t g_bucketp[(size_t)N_NODES * BUCKET_CAP];  // col:u16 | val:fp16
__device__ __nv_bfloat16 g_whi[256 * 256];
__device__ __nv_bfloat16 g_wlo[256 * 256];

__device__ __forceinline__ void split_bf16(float f, __nv_bfloat16& h, __nv_bfloat16& l) {
    h = __float2bfloat16(f);
    l = __float2bfloat16(f - __bfloat162float(h));
}
__device__ __forceinline__ uint32_t pack_bf16(__nv_bfloat16 a, __nv_bfloat16 b) {
    __nv_bfloat162 p; p.x = a; p.y = b;
    return *(uint32_t*)&p;
}

// ---------------- prep: zero counts + split W into bf16 hi/lo ----------------
__global__ void prep_kernel(const float* __restrict__ W) {
    int idx = blockIdx.x * blockDim.x + threadIdx.x;   // 65536 threads
    if (idx < N_NODES) g_count[idx] = 0;
    if (idx < 256 * 256) {
        __nv_bfloat16 h, l;
        split_bf16(W[idx], h, l);
        g_whi[idx] = h;
        g_wlo[idx] = l;
    }
}

// ---------------- fused kernel: interleaved GEMM tiles + bucket scatter ----------------
#define GBM 128
#define GBN 128
#define GBK 32
#define APAD 40
#define NGEMM_BLKS ((M_PAD / GBM) * (DIM / GBN))       // 391*2 = 782
#define NSCAT_BLKS ((N_EDGES + 255) / 256)             // 6250
#define NTOT_BLKS (NGEMM_BLKS * 9)                     // 7038: every 9th block = GEMM

__device__ __forceinline__ void mma16816(float* d, const uint32_t* a, const uint32_t* b) {
    asm volatile(
        "mma.sync.aligned.m16n8k16.row.col.f32.bf16.bf16.f32 "
        "{%0,%1,%2,%3}, {%4,%5,%6,%7}, {%8,%9}, {%0,%1,%2,%3};"
        : "+f"(d[0]), "+f"(d[1]), "+f"(d[2]), "+f"(d[3])
        : "r"(a[0]), "r"(a[1]), "r"(a[2]), "r"(a[3]), "r"(b[0]), "r"(b[1]));
}

__global__ __launch_bounds__(256) void fused_kernel(const float* __restrict__ x,
                                                    const int*   __restrict__ erow,
                                                    const int*   __restrict__ ecol,
                                                    const float* __restrict__ eval) {
    __shared__ __nv_bfloat16 Ah[GBM][APAD];
    __shared__ __nv_bfloat16 Al[GBM][APAD];
    __shared__ __nv_bfloat16 Bh[GBN][APAD];
    __shared__ __nv_bfloat16 Bl[GBN][APAD];

    const int bid = blockIdx.x;
    const int tid = threadIdx.x;
    const int gq = bid / 9;
    const int rr = bid - gq * 9;

    if (rr != 0) {
        // ---------- scatter path (8 of every 9 blocks) ----------
        int sb = gq * 8 + rr - 1;
        if (sb >= NSCAT_BLKS) return;
        int e = sb * 256 + tid;
        if (e < N_EDGES) {
            int r = erow[e];
            int pos = atomicAdd(&g_count[r], 1);
            if (pos < BUCKET_CAP) {
                __half hv = __float2half_rn(eval[e]);
                uint32_t p = (uint32_t)ecol[e] | ((uint32_t)(*(unsigned short*)&hv) << 16);
                g_bucketp[(size_t)r * BUCKET_CAP + pos] = p;
            }
        }
        return;
    }

    // ---------- GEMM path: y = x @ W^T, bf16x3 split, fp16 output ----------
    const int warp = tid >> 5;
    const int lane = tid & 31;
    const int wm = warp >> 2;          // 0..1
    const int wn = warp & 3;           // 0..3
    const int g = lane >> 2;           // 0..7
    const int t = lane & 3;            // 0..3

    const size_t bm = (size_t)(gq >> 1) * GBM;
    const int bn = (gq & 1) * GBN;

    const int arow[4] = { tid >> 3, (tid + 256) >> 3, (tid + 512) >> 3, (tid + 768) >> 3 };
    const int aseg = tid & 7;
    const int brow0 = tid >> 2, brow1 = (tid + 256) >> 2;
    const int bseg = tid & 3;

    float acc[4][4][4];
    #pragma unroll
    for (int i = 0; i < 4; i++)
        #pragma unroll
        for (int j = 0; j < 4; j++)
            #pragma unroll
            for (int r = 0; r < 4; r++) acc[i][j][r] = 0.f;

    float4 fa[4];
    uint4 fbh[2], fbl[2];

    auto load_tile = [&](int k0) {
        #pragma unroll
        for (int p = 0; p < 4; p++) {
            size_t gr = bm + arow[p];
            fa[p] = (gr < N_NODES)
                  ? *(const float4*)(x + gr * DIM + k0 + aseg * 4)
                  : make_float4(0.f, 0.f, 0.f, 0.f);
        }
        fbh[0] = *(const uint4*)(g_whi + (size_t)(bn + brow0) * DIM + k0 + bseg * 8);
        fbh[1] = *(const uint4*)(g_whi + (size_t)(bn + brow1) * DIM + k0 + bseg * 8);
        fbl[0] = *(const uint4*)(g_wlo + (size_t)(bn + brow0) * DIM + k0 + bseg * 8);
        fbl[1] = *(const uint4*)(g_wlo + (size_t)(bn + brow1) * DIM + k0 + bseg * 8);
    };
    auto store_tile = [&]() {
        #pragma unroll
        for (int p = 0; p < 4; p++) {
            float4 f = fa[p];
            __nv_bfloat16 h0, h1, h2, h3, l0, l1, l2, l3;
            split_bf16(f.x, h0, l0); split_bf16(f.y, h1, l1);
            split_bf16(f.z, h2, l2); split_bf16(f.w, h3, l3);
            uint2 hv, lv;
            hv.x = pack_bf16(h0, h1); hv.y = pack_bf16(h2, h3);
            lv.x = pack_bf16(l0, l1); lv.y = pack_bf16(l2, l3);
            *(uint2*)&Ah[arow[p]][aseg * 4] = hv;
            *(uint2*)&Al[arow[p]][aseg * 4] = lv;
        }
        *(uint4*)&Bh[brow0][bseg * 8] = fbh[0];
        *(uint4*)&Bh[brow1][bseg * 8] = fbh[1];
        *(uint4*)&Bl[brow0][bseg * 8] = fbl[0];
        *(uint4*)&Bl[brow1][bseg * 8] = fbl[1];
    };

    load_tile(0);
    store_tile();
    __syncthreads();

    for (int k0 = 0; k0 < DIM; k0 += GBK) {
        if (k0 + GBK < DIM) load_tile(k0 + GBK);     // prefetch next tile

        #pragma unroll
        for (int ks = 0; ks < 2; ks++) {
            const int kb = ks * 16;
            uint32_t bh[4][2], bl[4][2];
            #pragma unroll
            for (int ni = 0; ni < 4; ni++) {
                int c = wn * 32 + ni * 8 + g;
                bh[ni][0] = *(const uint32_t*)&Bh[c][kb + 2 * t];
                bh[ni][1] = *(const uint32_t*)&Bh[c][kb + 2 * t + 8];
                bl[ni][0] = *(const uint32_t*)&Bl[c][kb + 2 * t];
                bl[ni][1] = *(const uint32_t*)&Bl[c][kb + 2 * t + 8];
            }
            #pragma unroll
            for (int mi = 0; mi < 4; mi++) {
                int r = wm * 64 + mi * 16;
                uint32_t ah[4], al[4];
                ah[0] = *(const uint32_t*)&Ah[r + g][kb + 2 * t];
                ah[1] = *(const uint32_t*)&Ah[r + g + 8][kb + 2 * t];
                ah[2] = *(const uint32_t*)&Ah[r + g][kb + 2 * t + 8];
                ah[3] = *(const uint32_t*)&Ah[r + g + 8][kb + 2 * t + 8];
                al[0] = *(const uint32_t*)&Al[r + g][kb + 2 * t];
                al[1] = *(const uint32_t*)&Al[r + g + 8][kb + 2 * t];
                al[2] = *(const uint32_t*)&Al[r + g][kb + 2 * t + 8];
                al[3] = *(const uint32_t*)&Al[r + g + 8][kb + 2 * t + 8];
                #pragma unroll
                for (int ni = 0; ni < 4; ni++) {
                    mma16816(acc[mi][ni], ah, bh[ni]);   // hi*hi
                    mma16816(acc[mi][ni], ah, bl[ni]);   // hi*lo
                    mma16816(acc[mi][ni], al, bh[ni]);   // lo*hi
                }
            }
        }
        __syncthreads();
        if (k0 + GBK < DIM) {
            store_tile();
            __syncthreads();
        }
    }

    // epilogue: write fp16 y
    #pragma unroll
    for (int mi = 0; mi < 4; mi++) {
        size_t r0 = bm + wm * 64 + mi * 16 + g;
        size_t r1 = r0 + 8;
        #pragma unroll
        for (int ni = 0; ni < 4; ni++) {
            int c = bn + wn * 32 + ni * 8 + 2 * t;
            __half2 v0 = __floats2half2_rn(acc[mi][ni][0], acc[mi][ni][1]);
            __half2 v1 = __floats2half2_rn(acc[mi][ni][2], acc[mi][ni][3]);
            *(__half2*)(g_y + r0 * DIM + c) = v0;
            *(__half2*)(g_y + r1 * DIM + c) = v1;
        }
    }
}

// ---------------- aggregation: 1 warp per node, uint4 gathers, MLP=8 ----------------
__global__ __launch_bounds__(256) void aggregate_relu_kernel(float* __restrict__ out) {
    __shared__ uint32_t sp[8][BUCKET_CAP];
    const int warp = threadIdx.x >> 5;
    const int lane = threadIdx.x & 31;
    const int node = blockIdx.x * 8 + warp;   // 6250 * 8 = 50000 exactly

    int cnt = g_count[node];
    if (cnt > BUCKET_CAP) cnt = BUCKET_CAP;

    const uint32_t* bkt = g_bucketp + (size_t)node * BUCKET_CAP;
    for (int i = lane; i < cnt; i += 32) sp[warp][i] = bkt[i];
    __syncwarp();

    float acc[8];
    #pragma unroll
    for (int j = 0; j < 8; j++) acc[j] = 0.f;

    const int co = lane * 8;                  // fp16 feature offset (16 B per lane)
    int i = 0;
    for (; i + 8 <= cnt; i += 8) {
        uint32_t p[8];
        #pragma unroll
        for (int q = 0; q < 8; q++) p[q] = sp[warp][i + q];
        uint4 v[8];
        #pragma unroll
        for (int q = 0; q < 8; q++)
            v[q] = *(const uint4*)(g_y + (size_t)(p[q] & 0xFFFFu) * DIM + co);
        #pragma unroll
        for (int q = 0; q < 8; q++) {
            unsigned short hw = (unsigned short)(p[q] >> 16);
            float w = __half2float(*(__half*)&hw);
            float2 f0 = __half22float2(*(__half2*)&v[q].x);
            float2 f1 = __half22float2(*(__half2*)&v[q].y);
            float2 f2 = __half22float2(*(__half2*)&v[q].z);
            float2 f3 = __half22float2(*(__half2*)&v[q].w);
            acc[0] = fmaf(w, f0.x, acc[0]); acc[1] = fmaf(w, f0.y, acc[1]);
            acc[2] = fmaf(w, f1.x, acc[2]); acc[3] = fmaf(w, f1.y, acc[3]);
            acc[4] = fmaf(w, f2.x, acc[4]); acc[5] = fmaf(w, f2.y, acc[5]);
            acc[6] = fmaf(w, f3.x, acc[6]); acc[7] = fmaf(w, f3.y, acc[7]);
        }
    }
    for (; i < cnt; i++) {
        uint32_t p = sp[warp][i];
        unsigned short hw = (unsigned short)(p >> 16);
        float w = __half2float(*(__half*)&hw);
        uint4 v = *(const uint4*)(g_y + (size_t)(p & 0xFFFFu) * DIM + co);
        float2 f0 = __half22float2(*(__half2*)&v.x);
        float2 f1 = __half22float2(*(__half2*)&v.y);
        float2 f2 = __half22float2(*(__half2*)&v.z);
        float2 f3 = __half22float2(*(__half2*)&v.w);
        acc[0] = fmaf(w, f0.x, acc[0]); acc[1] = fmaf(w, f0.y, acc[1]);
        acc[2] = fmaf(w, f1.x, acc[2]); acc[3] = fmaf(w, f1.y, acc[3]);
        acc[4] = fmaf(w, f2.x, acc[4]); acc[5] = fmaf(w, f2.y, acc[5]);
        acc[6] = fmaf(w, f3.x, acc[6]); acc[7] = fmaf(w, f3.y, acc[7]);
    }

    float4 o0, o1;
    o0.x = fmaxf(acc[0], 0.f); o0.y = fmaxf(acc[1], 0.f);
    o0.z = fmaxf(acc[2], 0.f); o0.w = fmaxf(acc[3], 0.f);
    o1.x = fmaxf(acc[4], 0.f); o1.y = fmaxf(acc[5], 0.f);
    o1.z = fmaxf(acc[6], 0.f); o1.w = fmaxf(acc[7], 0.f);
    float* orow = out + (size_t)node * DIM + co;
    *(float4*)(orow + 0) = o0;
    *(float4*)(orow + 4) = o1;
}

extern "C" void kernel_launch(void* const* d_in, const int* in_sizes, int n_in,
                              void* d_out, int out_size) {
    const float* x    = (const float*)d_in[0];   // [N_NODES, 256]
    const int*   erow = (const int*)  d_in[1];   // [E]
    const int*   ecol = (const int*)  d_in[2];   // [E]
    const float* ev   = (const float*)d_in[3];   // [E]
    const float* W    = (const float*)d_in[4];   // [256, 256]
    float* out = (float*)d_out;                  // [N_NODES, 256]

    prep_kernel<<<256, 256>>>(W);
    fused_kernel<<<NTOT_BLKS, 256>>>(x, erow, ecol, ev);
    aggregate_relu_kernel<<<N_NODES / 8, 256>>>(out);
}

// round 7
// speedup vs baseline: 1.2758x; 1.2758x over previous
#include <cuda_runtime.h>
#include <cuda_bf16.h>
#include <cuda_fp16.h>
#include <cstdint>

#define N_NODES 50000
#define N_EDGES 1600000
#define DIM 256
#define M_PAD 50048              // 391 * 128
#define BUCKET_CAP 128

// ---- device scratch (no allocations allowed) ----
__device__ __half g_y[(size_t)M_PAD * DIM];         // y = x @ W^T  (fp16, 25.6 MB)
__device__ int   g_count[N_NODES];
__device__ uint2 g_bucket[(size_t)N_NODES * BUCKET_CAP];   // {col, val bits}
__device__ __nv_bfloat16 g_whi[256 * 256];
__device__ __nv_bfloat16 g_wlo[256 * 256];

__device__ __forceinline__ void split_bf16(float f, __nv_bfloat16& h, __nv_bfloat16& l) {
    h = __float2bfloat16(f);
    l = __float2bfloat16(f - __bfloat162float(h));
}
__device__ __forceinline__ uint32_t pack_bf16(__nv_bfloat16 a, __nv_bfloat16 b) {
    __nv_bfloat162 p; p.x = a; p.y = b;
    return *(uint32_t*)&p;
}

// ---------------- prep: zero counts + split W into bf16 hi/lo ----------------
__global__ void prep_kernel(const float* __restrict__ W) {
    int idx = blockIdx.x * blockDim.x + threadIdx.x;   // 65536 threads
    if (idx < N_NODES) g_count[idx] = 0;
    if (idx < 256 * 256) {
        __nv_bfloat16 h, l;
        split_bf16(W[idx], h, l);
        g_whi[idx] = h;
        g_wlo[idx] = l;
    }
}

// ---------------- scatter: standalone, low-register, high-occupancy ----------------
__global__ __launch_bounds__(256) void scatter_kernel(const int*   __restrict__ erow,
                                                      const int*   __restrict__ ecol,
                                                      const float* __restrict__ eval) {
    int e = blockIdx.x * 256 + threadIdx.x;
    if (e < N_EDGES) {
        int r = erow[e];
        int c = ecol[e];              // issue all three loads before the atomic
        float v = eval[e];
        int pos = atomicAdd(&g_count[r], 1);
        if (pos < BUCKET_CAP) {
            uint2 p;
            p.x = (uint32_t)c;
            p.y = __float_as_uint(v);
            g_bucket[(size_t)r * BUCKET_CAP + pos] = p;
        }
    }
}

// ---------------- GEMM: y = x @ W^T, bf16x3 split, fp16 output ----------------
#define GBM 128
#define GBN 128
#define GBK 32
#define APAD 40
#define NGEMM_BLKS ((M_PAD / GBM) * (DIM / GBN))       // 391*2 = 782
#define NSCAT_BLKS ((N_EDGES + 255) / 256)             // 6250

__device__ __forceinline__ void mma16816(float* d, const uint32_t* a, const uint32_t* b) {
    asm volatile(
        "mma.sync.aligned.m16n8k16.row.col.f32.bf16.bf16.f32 "
        "{%0,%1,%2,%3}, {%4,%5,%6,%7}, {%8,%9}, {%0,%1,%2,%3};"
        : "+f"(d[0]), "+f"(d[1]), "+f"(d[2]), "+f"(d[3])
        : "r"(a[0]), "r"(a[1]), "r"(a[2]), "r"(a[3]), "r"(b[0]), "r"(b[1]));
}

__global__ __launch_bounds__(256) void gemm_kernel(const float* __restrict__ x) {
    __shared__ __nv_bfloat16 Ah[GBM][APAD];
    __shared__ __nv_bfloat16 Al[GBM][APAD];
    __shared__ __nv_bfloat16 Bh[GBN][APAD];
    __shared__ __nv_bfloat16 Bl[GBN][APAD];

    const int bid = blockIdx.x;
    const int tid = threadIdx.x;
    const int warp = tid >> 5;
    const int lane = tid & 31;
    const int wm = warp >> 2;          // 0..1
    const int wn = warp & 3;           // 0..3
    const int g = lane >> 2;           // 0..7
    const int t = lane & 3;            // 0..3

    const size_t bm = (size_t)(bid >> 1) * GBM;
    const int bn = (bid & 1) * GBN;

    const int arow[4] = { tid >> 3, (tid + 256) >> 3, (tid + 512) >> 3, (tid + 768) >> 3 };
    const int aseg = tid & 7;
    const int brow0 = tid >> 2, brow1 = (tid + 256) >> 2;
    const int bseg = tid & 3;

    float acc[4][4][4];
    #pragma unroll
    for (int i = 0; i < 4; i++)
        #pragma unroll
        for (int j = 0; j < 4; j++)
            #pragma unroll
            for (int r = 0; r < 4; r++) acc[i][j][r] = 0.f;

    float4 fa[4];
    uint4 fbh[2], fbl[2];

    auto load_tile = [&](int k0) {
        #pragma unroll
        for (int p = 0; p < 4; p++) {
            size_t gr = bm + arow[p];
            fa[p] = (gr < N_NODES)
                  ? *(const float4*)(x + gr * DIM + k0 + aseg * 4)
                  : make_float4(0.f, 0.f, 0.f, 0.f);
        }
        fbh[0] = *(const uint4*)(g_whi + (size_t)(bn + brow0) * DIM + k0 + bseg * 8);
        fbh[1] = *(const uint4*)(g_whi + (size_t)(bn + brow1) * DIM + k0 + bseg * 8);
        fbl[0] = *(const uint4*)(g_wlo + (size_t)(bn + brow0) * DIM + k0 + bseg * 8);
        fbl[1] = *(const uint4*)(g_wlo + (size_t)(bn + brow1) * DIM + k0 + bseg * 8);
    };
    auto store_tile = [&]() {
        #pragma unroll
        for (int p = 0; p < 4; p++) {
            float4 f = fa[p];
            __nv_bfloat16 h0, h1, h2, h3, l0, l1, l2, l3;
            split_bf16(f.x, h0, l0); split_bf16(f.y, h1, l1);
            split_bf16(f.z, h2, l2); split_bf16(f.w, h3, l3);
            uint2 hv, lv;
            hv.x = pack_bf16(h0, h1); hv.y = pack_bf16(h2, h3);
            lv.x = pack_bf16(l0, l1); lv.y = pack_bf16(l2, l3);
            *(uint2*)&Ah[arow[p]][aseg * 4] = hv;
            *(uint2*)&Al[arow[p]][aseg * 4] = lv;
        }
        *(uint4*)&Bh[brow0][bseg * 8] = fbh[0];
        *(uint4*)&Bh[brow1][bseg * 8] = fbh[1];
        *(uint4*)&Bl[brow0][bseg * 8] = fbl[0];
        *(uint4*)&Bl[brow1][bseg * 8] = fbl[1];
    };

    load_tile(0);
    store_tile();
    __syncthreads();

    for (int k0 = 0; k0 < DIM; k0 += GBK) {
        if (k0 + GBK < DIM) load_tile(k0 + GBK);     // prefetch next tile

        #pragma unroll
        for (int ks = 0; ks < 2; ks++) {
            const int kb = ks * 16;
            uint32_t bh[4][2], bl[4][2];
            #pragma unroll
            for (int ni = 0; ni < 4; ni++) {
                int c = wn * 32 + ni * 8 + g;
                bh[ni][0] = *(const uint32_t*)&Bh[c][kb + 2 * t];
                bh[ni][1] = *(const uint32_t*)&Bh[c][kb + 2 * t + 8];
                bl[ni][0] = *(const uint32_t*)&Bl[c][kb + 2 * t];
                bl[ni][1] = *(const uint32_t*)&Bl[c][kb + 2 * t + 8];
            }
            #pragma unroll
            for (int mi = 0; mi < 4; mi++) {
                int r = wm * 64 + mi * 16;
                uint32_t ah[4], al[4];
                ah[0] = *(const uint32_t*)&Ah[r + g][kb + 2 * t];
                ah[1] = *(const uint32_t*)&Ah[r + g + 8][kb + 2 * t];
                ah[2] = *(const uint32_t*)&Ah[r + g][kb + 2 * t + 8];
                ah[3] = *(const uint32_t*)&Ah[r + g + 8][kb + 2 * t + 8];
                al[0] = *(const uint32_t*)&Al[r + g][kb + 2 * t];
                al[1] = *(const uint32_t*)&Al[r + g + 8][kb + 2 * t];
                al[2] = *(const uint32_t*)&Al[r + g][kb + 2 * t + 8];
                al[3] = *(const uint32_t*)&Al[r + g + 8][kb + 2 * t + 8];
                #pragma unroll
                for (int ni = 0; ni < 4; ni++) {
                    mma16816(acc[mi][ni], ah, bh[ni]);   // hi*hi
                    mma16816(acc[mi][ni], ah, bl[ni]);   // hi*lo
                    mma16816(acc[mi][ni], al, bh[ni]);   // lo*hi
                }
            }
        }
        __syncthreads();
        if (k0 + GBK < DIM) {
            store_tile();
            __syncthreads();
        }
    }

    // epilogue: write fp16 y
    #pragma unroll
    for (int mi = 0; mi < 4; mi++) {
        size_t r0 = bm + wm * 64 + mi * 16 + g;
        size_t r1 = r0 + 8;
        #pragma unroll
        for (int ni = 0; ni < 4; ni++) {
            int c = bn + wn * 32 + ni * 8 + 2 * t;
            __half2 v0 = __floats2half2_rn(acc[mi][ni][0], acc[mi][ni][1]);
            __half2 v1 = __floats2half2_rn(acc[mi][ni][2], acc[mi][ni][3]);
            *(__half2*)(g_y + r0 * DIM + c) = v0;
            *(__half2*)(g_y + r1 * DIM + c) = v1;
        }
    }
}

// ---------------- aggregation: 1 warp per node, uint4 gathers, MLP=4 ----------------
__global__ __launch_bounds__(256) void aggregate_relu_kernel(float* __restrict__ out) {
    __shared__ uint2 sp[8][BUCKET_CAP];
    const int warp = threadIdx.x >> 5;
    const int lane = threadIdx.x & 31;
    const int node = blockIdx.x * 8 + warp;   // 6250 * 8 = 50000 exactly

    int cnt = g_count[node];
    if (cnt > BUCKET_CAP) cnt = BUCKET_CAP;

    const uint2* bkt = g_bucket + (size_t)node * BUCKET_CAP;
    for (int i = lane; i < cnt; i += 32) sp[warp][i] = bkt[i];
    __syncwarp();

    float acc[8];
    #pragma unroll
    for (int j = 0; j < 8; j++) acc[j] = 0.f;

    const int co = lane * 8;                  // fp16 feature offset for this lane (16 B)
    int i = 0;
    for (; i + 4 <= cnt; i += 4) {
        uint2 e0 = sp[warp][i + 0];
        uint2 e1 = sp[warp][i + 1];
        uint2 e2 = sp[warp][i + 2];
        uint2 e3 = sp[warp][i + 3];
        uint4 v0 = *(const uint4*)(g_y + (size_t)e0.x * DIM + co);
        uint4 v1 = *(const uint4*)(g_y + (size_t)e1.x * DIM + co);
        uint4 v2 = *(const uint4*)(g_y + (size_t)e2.x * DIM + co);
        uint4 v3 = *(const uint4*)(g_y + (size_t)e3.x * DIM + co);
        #pragma unroll
        for (int q = 0; q < 4; q++) {
            uint4 v = (q == 0) ? v0 : (q == 1) ? v1 : (q == 2) ? v2 : v3;
            float w = __uint_as_float((q == 0 ? e0 : q == 1 ? e1 : q == 2 ? e2 : e3).y);
            float2 f0 = __half22float2(*(__half2*)&v.x);
            float2 f1 = __half22float2(*(__half2*)&v.y);
            float2 f2 = __half22float2(*(__half2*)&v.z);
            float2 f3 = __half22float2(*(__half2*)&v.w);
            acc[0] = fmaf(w, f0.x, acc[0]); acc[1] = fmaf(w, f0.y, acc[1]);
            acc[2] = fmaf(w, f1.x, acc[2]); acc[3] = fmaf(w, f1.y, acc[3]);
            acc[4] = fmaf(w, f2.x, acc[4]); acc[5] = fmaf(w, f2.y, acc[5]);
            acc[6] = fmaf(w, f3.x, acc[6]); acc[7] = fmaf(w, f3.y, acc[7]);
        }
    }
    for (; i < cnt; i++) {
        uint2 e = sp[warp][i];
        float w = __uint_as_float(e.y);
        uint4 v = *(const uint4*)(g_y + (size_t)e.x * DIM + co);
        float2 f0 = __half22float2(*(__half2*)&v.x);
        float2 f1 = __half22float2(*(__half2*)&v.y);
        float2 f2 = __half22float2(*(__half2*)&v.z);
        float2 f3 = __half22float2(*(__half2*)&v.w);
        acc[0] = fmaf(w, f0.x, acc[0]); acc[1] = fmaf(w, f0.y, acc[1]);
        acc[2] = fmaf(w, f1.x, acc[2]); acc[3] = fmaf(w, f1.y, acc[3]);
        acc[4] = fmaf(w, f2.x, acc[4]); acc[5] = fmaf(w, f2.y, acc[5]);
        acc[6] = fmaf(w, f3.x, acc[6]); acc[7] = fmaf(w, f3.y, acc[7]);
    }

    float4 o0, o1;
    o0.x = fmaxf(acc[0], 0.f); o0.y = fmaxf(acc[1], 0.f);
    o0.z = fmaxf(acc[2], 0.f); o0.w = fmaxf(acc[3], 0.f);
    o1.x = fmaxf(acc[4], 0.f); o1.y = fmaxf(acc[5], 0.f);
    o1.z = fmaxf(acc[6], 0.f); o1.w = fmaxf(acc[7], 0.f);
    float* orow = out + (size_t)node * DIM + co;
    *(float4*)(orow + 0) = o0;
    *(float4*)(orow + 4) = o1;
}

extern "C" void kernel_launch(void* const* d_in, const int* in_sizes, int n_in,
                              void* d_out, int out_size) {
    const float* x    = (const float*)d_in[0];   // [N_NODES, 256]
    const int*   erow = (const int*)  d_in[1];   // [E]
    const int*   ecol = (const int*)  d_in[2];   // [E]
    const float* ev   = (const float*)d_in[3];   // [E]
    const float* W    = (const float*)d_in[4];   // [256, 256]
    float* out = (float*)d_out;                  // [N_NODES, 256]

    prep_kernel<<<256, 256>>>(W);
    scatter_kernel<<<NSCAT_BLKS, 256>>>(erow, ecol, ev);
    gemm_kernel<<<NGEMM_BLKS, 256>>>(x);
    aggregate_relu_kernel<<<N_NODES / 8, 256>>>(out);
}

// round 8
// speedup vs baseline: 1.5302x; 1.1995x over previous
#include <cuda_runtime.h>
#include <cuda_fp16.h>
#include <cstdint>

#define N_NODES 50000
#define N_EDGES 1600000
#define DIM 256
#define M_PAD 50048              // 391 * 128
#define BUCKET_CAP 128

// ---- device scratch (no allocations allowed) ----
__device__ __half g_y[(size_t)M_PAD * DIM];         // y = x @ W^T  (fp16, 25.6 MB)
__device__ int   g_count[N_NODES];
__device__ uint2 g_bucket[(size_t)N_NODES * BUCKET_CAP];   // {col, val bits}
__device__ __half g_wh[256 * 256];                  // W in fp16

// ---------------- prep: zero counts + convert W to fp16 ----------------
__global__ void prep_kernel(const float* __restrict__ W) {
    int idx = blockIdx.x * blockDim.x + threadIdx.x;   // 65536 threads
    if (idx < N_NODES) g_count[idx] = 0;
    if (idx < 256 * 256) g_wh[idx] = __float2half_rn(W[idx]);
}

// ---------------- scatter: standalone, low-register, high-occupancy ----------------
__global__ __launch_bounds__(256) void scatter_kernel(const int*   __restrict__ erow,
                                                      const int*   __restrict__ ecol,
                                                      const float* __restrict__ eval) {
    int e = blockIdx.x * 256 + threadIdx.x;
    if (e < N_EDGES) {
        int r = erow[e];
        int c = ecol[e];              // issue all three loads before the atomic
        float v = eval[e];
        int pos = atomicAdd(&g_count[r], 1);
        if (pos < BUCKET_CAP) {
            uint2 p;
            p.x = (uint32_t)c;
            p.y = __float_as_uint(v);
            g_bucket[(size_t)r * BUCKET_CAP + pos] = p;
        }
    }
}

// ---------------- GEMM: y = x @ W^T, single-pass fp16 MMA, fp32 accum ----------------
#define GBM 128
#define GBN 128
#define GBK 32
#define APAD 40
#define NGEMM_BLKS ((M_PAD / GBM) * (DIM / GBN))       // 391*2 = 782
#define NSCAT_BLKS ((N_EDGES + 255) / 256)             // 6250

__device__ __forceinline__ void mma16816f16(float* d, const uint32_t* a, const uint32_t* b) {
    asm volatile(
        "mma.sync.aligned.m16n8k16.row.col.f32.f16.f16.f32 "
        "{%0,%1,%2,%3}, {%4,%5,%6,%7}, {%8,%9}, {%0,%1,%2,%3};"
        : "+f"(d[0]), "+f"(d[1]), "+f"(d[2]), "+f"(d[3])
        : "r"(a[0]), "r"(a[1]), "r"(a[2]), "r"(a[3]), "r"(b[0]), "r"(b[1]));
}

__global__ __launch_bounds__(256) void gemm_kernel(const float* __restrict__ x) {
    __shared__ __half Ah[GBM][APAD];
    __shared__ __half Bh[GBN][APAD];

    const int bid = blockIdx.x;
    const int tid = threadIdx.x;
    const int warp = tid >> 5;
    const int lane = tid & 31;
    const int wm = warp >> 2;          // 0..1
    const int wn = warp & 3;           // 0..3
    const int g = lane >> 2;           // 0..7
    const int t = lane & 3;            // 0..3

    const size_t bm = (size_t)(bid >> 1) * GBM;
    const int bn = (bid & 1) * GBN;

    const int arow[4] = { tid >> 3, (tid + 256) >> 3, (tid + 512) >> 3, (tid + 768) >> 3 };
    const int aseg = tid & 7;
    const int brow0 = tid >> 2, brow1 = (tid + 256) >> 2;
    const int bseg = tid & 3;

    float acc[4][4][4];
    #pragma unroll
    for (int i = 0; i < 4; i++)
        #pragma unroll
        for (int j = 0; j < 4; j++)
            #pragma unroll
            for (int r = 0; r < 4; r++) acc[i][j][r] = 0.f;

    float4 fa[4];
    uint4 fbh[2];

    auto load_tile = [&](int k0) {
        #pragma unroll
        for (int p = 0; p < 4; p++) {
            size_t gr = bm + arow[p];
            fa[p] = (gr < N_NODES)
                  ? *(const float4*)(x + gr * DIM + k0 + aseg * 4)
                  : make_float4(0.f, 0.f, 0.f, 0.f);
        }
        fbh[0] = *(const uint4*)(g_wh + (size_t)(bn + brow0) * DIM + k0 + bseg * 8);
        fbh[1] = *(const uint4*)(g_wh + (size_t)(bn + brow1) * DIM + k0 + bseg * 8);
    };
    auto store_tile = [&]() {
        #pragma unroll
        for (int p = 0; p < 4; p++) {
            float4 f = fa[p];
            __half2 h0 = __floats2half2_rn(f.x, f.y);
            __half2 h1 = __floats2half2_rn(f.z, f.w);
            uint2 hv;
            hv.x = *(uint32_t*)&h0;
            hv.y = *(uint32_t*)&h1;
            *(uint2*)&Ah[arow[p]][aseg * 4] = hv;
        }
        *(uint4*)&Bh[brow0][bseg * 8] = fbh[0];
        *(uint4*)&Bh[brow1][bseg * 8] = fbh[1];
    };

    load_tile(0);
    store_tile();
    __syncthreads();

    for (int k0 = 0; k0 < DIM; k0 += GBK) {
        if (k0 + GBK < DIM) load_tile(k0 + GBK);     // prefetch next tile

        #pragma unroll
        for (int ks = 0; ks < 2; ks++) {
            const int kb = ks * 16;
            uint32_t bh[4][2];
            #pragma unroll
            for (int ni = 0; ni < 4; ni++) {
                int c = wn * 32 + ni * 8 + g;
                bh[ni][0] = *(const uint32_t*)&Bh[c][kb + 2 * t];
                bh[ni][1] = *(const uint32_t*)&Bh[c][kb + 2 * t + 8];
            }
            #pragma unroll
            for (int mi = 0; mi < 4; mi++) {
                int r = wm * 64 + mi * 16;
                uint32_t ah[4];
                ah[0] = *(const uint32_t*)&Ah[r + g][kb + 2 * t];
                ah[1] = *(const uint32_t*)&Ah[r + g + 8][kb + 2 * t];
                ah[2] = *(const uint32_t*)&Ah[r + g][kb + 2 * t + 8];
                ah[3] = *(const uint32_t*)&Ah[r + g + 8][kb + 2 * t + 8];
                #pragma unroll
                for (int ni = 0; ni < 4; ni++) {
                    mma16816f16(acc[mi][ni], ah, bh[ni]);
                }
            }
        }
        __syncthreads();
        if (k0 + GBK < DIM) {
            store_tile();
            __syncthreads();
        }
    }

    // epilogue: write fp16 y
    #pragma unroll
    for (int mi = 0; mi < 4; mi++) {
        size_t r0 = bm + wm * 64 + mi * 16 + g;
        size_t r1 = r0 + 8;
        #pragma unroll
        for (int ni = 0; ni < 4; ni++) {
            int c = bn + wn * 32 + ni * 8 + 2 * t;
            __half2 v0 = __floats2half2_rn(acc[mi][ni][0], acc[mi][ni][1]);
            __half2 v1 = __floats2half2_rn(acc[mi][ni][2], acc[mi][ni][3]);
            *(__half2*)(g_y + r0 * DIM + c) = v0;
            *(__half2*)(g_y + r1 * DIM + c) = v1;
        }
    }
}

// ---------------- aggregation: 1 warp per node, uint4 gathers, MLP=4 ----------------
__global__ __launch_bounds__(256) void aggregate_relu_kernel(float* __restrict__ out) {
    __shared__ uint2 sp[8][BUCKET_CAP];
    const int warp = threadIdx.x >> 5;
    const int lane = threadIdx.x & 31;
    const int node = blockIdx.x * 8 + warp;   // 6250 * 8 = 50000 exactly

    int cnt = g_count[node];
    if (cnt > BUCKET_CAP) cnt = BUCKET_CAP;

    const uint2* bkt = g_bucket + (size_t)node * BUCKET_CAP;
    for (int i = lane; i < cnt; i += 32) sp[warp][i] = bkt[i];
    __syncwarp();

    float acc[8];
    #pragma unroll
    for (int j = 0; j < 8; j++) acc[j] = 0.f;

    const int co = lane * 8;                  // fp16 feature offset for this lane (16 B)
    int i = 0;
    for (; i + 4 <= cnt; i += 4) {
        uint2 e0 = sp[warp][i + 0];
        uint2 e1 = sp[warp][i + 1];
        uint2 e2 = sp[warp][i + 2];
        uint2 e3 = sp[warp][i + 3];
        uint4 v0 = *(const uint4*)(g_y + (size_t)e0.x * DIM + co);
        uint4 v1 = *(const uint4*)(g_y + (size_t)e1.x * DIM + co);
        uint4 v2 = *(const uint4*)(g_y + (size_t)e2.x * DIM + co);
        uint4 v3 = *(const uint4*)(g_y + (size_t)e3.x * DIM + co);
        #pragma unroll
        for (int q = 0; q < 4; q++) {
            uint4 v = (q == 0) ? v0 : (q == 1) ? v1 : (q == 2) ? v2 : v3;
            float w = __uint_as_float((q == 0 ? e0 : q == 1 ? e1 : q == 2 ? e2 : e3).y);
            float2 f0 = __half22float2(*(__half2*)&v.x);
            float2 f1 = __half22float2(*(__half2*)&v.y);
            float2 f2 = __half22float2(*(__half2*)&v.z);
            float2 f3 = __half22float2(*(__half2*)&v.w);
            acc[0] = fmaf(w, f0.x, acc[0]); acc[1] = fmaf(w, f0.y, acc[1]);
            acc[2] = fmaf(w, f1.x, acc[2]); acc[3] = fmaf(w, f1.y, acc[3]);
            acc[4] = fmaf(w, f2.x, acc[4]); acc[5] = fmaf(w, f2.y, acc[5]);
            acc[6] = fmaf(w, f3.x, acc[6]); acc[7] = fmaf(w, f3.y, acc[7]);
        }
    }
    for (; i < cnt; i++) {
        uint2 e = sp[warp][i];
        float w = __uint_as_float(e.y);
        uint4 v = *(const uint4*)(g_y + (size_t)e.x * DIM + co);
        float2 f0 = __half22float2(*(__half2*)&v.x);
        float2 f1 = __half22float2(*(__half2*)&v.y);
        float2 f2 = __half22float2(*(__half2*)&v.z);
        float2 f3 = __half22float2(*(__half2*)&v.w);
        acc[0] = fmaf(w, f0.x, acc[0]); acc[1] = fmaf(w, f0.y, acc[1]);
        acc[2] = fmaf(w, f1.x, acc[2]); acc[3] = fmaf(w, f1.y, acc[3]);
        acc[4] = fmaf(w, f2.x, acc[4]); acc[5] = fmaf(w, f2.y, acc[5]);
        acc[6] = fmaf(w, f3.x, acc[6]); acc[7] = fmaf(w, f3.y, acc[7]);
    }

    float4 o0, o1;
    o0.x = fmaxf(acc[0], 0.f); o0.y = fmaxf(acc[1], 0.f);
    o0.z = fmaxf(acc[2], 0.f); o0.w = fmaxf(acc[3], 0.f);
    o1.x = fmaxf(acc[4], 0.f); o1.y = fmaxf(acc[5], 0.f);
    o1.z = fmaxf(acc[6], 0.f); o1.w = fmaxf(acc[7], 0.f);
    float* orow = out + (size_t)node * DIM + co;
    *(float4*)(orow + 0) = o0;
    *(float4*)(orow + 4) = o1;
}

extern "C" void kernel_launch(void* const* d_in, const int* in_sizes, int n_in,
                              void* d_out, int out_size) {
    const float* x    = (const float*)d_in[0];   // [N_NODES, 256]
    const int*   erow = (const int*)  d_in[1];   // [E]
    const int*   ecol = (const int*)  d_in[2];   // [E]
    const float* ev   = (const float*)d_in[3];   // [E]
    const float* W    = (const float*)d_in[4];   // [256, 256]
    float* out = (float*)d_out;                  // [N_NODES, 256]

    prep_kernel<<<256, 256>>>(W);
    scatter_kernel<<<NSCAT_BLKS, 256>>>(erow, ecol, ev);
    gemm_kernel<<<NGEMM_BLKS, 256>>>(x);
    aggregate_relu_kernel<<<N_NODES / 8, 256>>>(out);
}

// round 9
// speedup vs baseline: 1.6041x; 1.0482x over previous
#include <cuda_runtime.h>
#include <cuda_fp16.h>
#include <cstdint>

#define N_NODES 50000
#define N_EDGES 1600000
#define DIM 256
#define M_PAD 50048              // 391 * 128
#define BUCKET_CAP 128

// ---- device scratch (no allocations allowed) ----
__device__ __half g_y[(size_t)M_PAD * DIM];         // y = x @ W^T  (fp16, 25.6 MB)
__device__ int   g_count[N_NODES];
__device__ uint2 g_bucket[(size_t)N_NODES * BUCKET_CAP];   // {col, val bits}
__device__ __half g_xh[(size_t)M_PAD * DIM];        // x in fp16, zero-padded
__device__ __half g_wh[256 * 256];                  // W in fp16

// ---------------- prep A: zero counts (scatter chain) ----------------
__global__ void zero_counts_kernel() {
    int i = blockIdx.x * blockDim.x + threadIdx.x;
    if (i < N_NODES) g_count[i] = 0;
}

// ---------------- prep B: convert x and W to fp16 (GEMM chain) ----------------
__global__ __launch_bounds__(256) void conv_xw_kernel(const float* __restrict__ x,
                                                      const float* __restrict__ W) {
    int idx = blockIdx.x * 256 + threadIdx.x;        // over M_PAD*64
    if (idx < 256 * 256) g_wh[idx] = __float2half_rn(W[idx]);
    if (idx >= M_PAD * 64) return;
    int row = idx >> 6;
    int c4 = (idx & 63) * 4;
    float4 f = make_float4(0.f, 0.f, 0.f, 0.f);
    if (row < N_NODES) f = *(const float4*)(x + (size_t)row * DIM + c4);
    __half2 h0 = __floats2half2_rn(f.x, f.y);
    __half2 h1 = __floats2half2_rn(f.z, f.w);
    uint2 v;
    v.x = *(uint32_t*)&h0;
    v.y = *(uint32_t*)&h1;
    *(uint2*)(g_xh + (size_t)row * DIM + c4) = v;
}

// ---------------- scatter: standalone, low-register, high-occupancy ----------------
__global__ __launch_bounds__(256) void scatter_kernel(const int*   __restrict__ erow,
                                                      const int*   __restrict__ ecol,
                                                      const float* __restrict__ eval) {
    int e = blockIdx.x * 256 + threadIdx.x;
    if (e < N_EDGES) {
        int r = erow[e];
        int c = ecol[e];              // issue all three loads before the atomic
        float v = eval[e];
        int pos = atomicAdd(&g_count[r], 1);
        if (pos < BUCKET_CAP) {
            uint2 p;
            p.x = (uint32_t)c;
            p.y = __float_as_uint(v);
            g_bucket[(size_t)r * BUCKET_CAP + pos] = p;
        }
    }
}

// ---------------- GEMM: y = x @ W^T, fp16 MMA, cp.async 2-stage pipeline ----------------
#define GBM 128
#define GBN 128
#define GBK 32
#define APAD 40   // fp16 elems per smem row (80 B = 5*16 -> cp.async-aligned, conflict-free)
#define NGEMM_BLKS ((M_PAD / GBM) * (DIM / GBN))       // 391*2 = 782
#define NSCAT_BLKS ((N_EDGES + 255) / 256)             // 6250

__device__ __forceinline__ void mma16816f16(float* d, const uint32_t* a, const uint32_t* b) {
    asm volatile(
        "mma.sync.aligned.m16n8k16.row.col.f32.f16.f16.f32 "
        "{%0,%1,%2,%3}, {%4,%5,%6,%7}, {%8,%9}, {%0,%1,%2,%3};"
        : "+f"(d[0]), "+f"(d[1]), "+f"(d[2]), "+f"(d[3])
        : "r"(a[0]), "r"(a[1]), "r"(a[2]), "r"(a[3]), "r"(b[0]), "r"(b[1]));
}
__device__ __forceinline__ void cp16(void* smem_dst, const void* gsrc) {
    uint32_t d = (uint32_t)__cvta_generic_to_shared(smem_dst);
    asm volatile("cp.async.cg.shared.global [%0], [%1], 16;" :: "r"(d), "l"(gsrc));
}
#define CP_COMMIT() asm volatile("cp.async.commit_group;" ::: "memory")
#define CP_WAIT0()  asm volatile("cp.async.wait_group 0;" ::: "memory")

__global__ __launch_bounds__(256) void gemm_kernel() {
    __shared__ __align__(16) __half Ah[2][GBM][APAD];
    __shared__ __align__(16) __half Bh[2][GBN][APAD];

    const int bid = blockIdx.x;
    const int tid = threadIdx.x;
    const int warp = tid >> 5;
    const int lane = tid & 31;
    const int wm = warp >> 2;          // 0..1
    const int wn = warp & 3;           // 0..3
    const int g = lane >> 2;           // 0..7
    const int t = lane & 3;            // 0..3

    const size_t bm = (size_t)(bid >> 1) * GBM;
    const int bn = (bid & 1) * GBN;

    // copy indexing: 512 16B-chunks per tile, 2 per thread per tile
    const int crow0 = tid >> 1,           cseg0 = (tid & 1) * 2;      // segs 0,1 or 2,3... see below
    // use chunks c = tid and c = tid + 256: row=c>>2, seg=c&3
    const int r0 = tid >> 2,          s0 = tid & 3;
    const int r1 = (tid + 256) >> 2,  s1 = (tid + 256) & 3;
    (void)crow0; (void)cseg0;

    auto copy_tile = [&](int st, int k0) {
        cp16(&Ah[st][r0][s0 * 8], g_xh + (bm + r0) * DIM + k0 + s0 * 8);
        cp16(&Ah[st][r1][s1 * 8], g_xh + (bm + r1) * DIM + k0 + s1 * 8);
        cp16(&Bh[st][r0][s0 * 8], g_wh + (size_t)(bn + r0) * DIM + k0 + s0 * 8);
        cp16(&Bh[st][r1][s1 * 8], g_wh + (size_t)(bn + r1) * DIM + k0 + s1 * 8);
    };

    float acc[4][4][4];
    #pragma unroll
    for (int i = 0; i < 4; i++)
        #pragma unroll
        for (int j = 0; j < 4; j++)
            #pragma unroll
            for (int r = 0; r < 4; r++) acc[i][j][r] = 0.f;

    copy_tile(0, 0);
    CP_COMMIT();

    #pragma unroll 1
    for (int it = 0; it < DIM / GBK; it++) {
        const int st = it & 1;
        CP_WAIT0();
        __syncthreads();
        if (it + 1 < DIM / GBK) {
            copy_tile(st ^ 1, (it + 1) * GBK);
            CP_COMMIT();
        }

        #pragma unroll
        for (int ks = 0; ks < 2; ks++) {
            const int kb = ks * 16;
            uint32_t bf[4][2];
            #pragma unroll
            for (int ni = 0; ni < 4; ni++) {
                int c = wn * 32 + ni * 8 + g;
                bf[ni][0] = *(const uint32_t*)&Bh[st][c][kb + 2 * t];
                bf[ni][1] = *(const uint32_t*)&Bh[st][c][kb + 2 * t + 8];
            }
            #pragma unroll
            for (int mi = 0; mi < 4; mi++) {
                int r = wm * 64 + mi * 16;
                uint32_t af[4];
                af[0] = *(const uint32_t*)&Ah[st][r + g][kb + 2 * t];
                af[1] = *(const uint32_t*)&Ah[st][r + g + 8][kb + 2 * t];
                af[2] = *(const uint32_t*)&Ah[st][r + g][kb + 2 * t + 8];
                af[3] = *(const uint32_t*)&Ah[st][r + g + 8][kb + 2 * t + 8];
                #pragma unroll
                for (int ni = 0; ni < 4; ni++) {
                    mma16816f16(acc[mi][ni], af, bf[ni]);
                }
            }
        }
    }

    // epilogue: write fp16 y
    #pragma unroll
    for (int mi = 0; mi < 4; mi++) {
        size_t rr0 = bm + wm * 64 + mi * 16 + g;
        size_t rr1 = rr0 + 8;
        #pragma unroll
        for (int ni = 0; ni < 4; ni++) {
            int c = bn + wn * 32 + ni * 8 + 2 * t;
            __half2 v0 = __floats2half2_rn(acc[mi][ni][0], acc[mi][ni][1]);
            __half2 v1 = __floats2half2_rn(acc[mi][ni][2], acc[mi][ni][3]);
            *(__half2*)(g_y + rr0 * DIM + c) = v0;
            *(__half2*)(g_y + rr1 * DIM + c) = v1;
        }
    }
}

// ---------------- aggregation: 1 warp per node, uint4 gathers, MLP=4 ----------------
__global__ __launch_bounds__(256) void aggregate_relu_kernel(float* __restrict__ out) {
    __shared__ uint2 sp[8][BUCKET_CAP];
    const int warp = threadIdx.x >> 5;
    const int lane = threadIdx.x & 31;
    const int node = blockIdx.x * 8 + warp;   // 6250 * 8 = 50000 exactly

    int cnt = g_count[node];
    if (cnt > BUCKET_CAP) cnt = BUCKET_CAP;

    const uint2* bkt = g_bucket + (size_t)node * BUCKET_CAP;
    for (int i = lane; i < cnt; i += 32) sp[warp][i] = bkt[i];
    __syncwarp();

    float acc[8];
    #pragma unroll
    for (int j = 0; j < 8; j++) acc[j] = 0.f;

    const int co = lane * 8;                  // fp16 feature offset for this lane (16 B)
    int i = 0;
    for (; i + 4 <= cnt; i += 4) {
        uint2 e0 = sp[warp][i + 0];
        uint2 e1 = sp[warp][i + 1];
        uint2 e2 = sp[warp][i + 2];
        uint2 e3 = sp[warp][i + 3];
        uint4 v0 = *(const uint4*)(g_y + (size_t)e0.x * DIM + co);
        uint4 v1 = *(const uint4*)(g_y + (size_t)e1.x * DIM + co);
        uint4 v2 = *(const uint4*)(g_y + (size_t)e2.x * DIM + co);
        uint4 v3 = *(const uint4*)(g_y + (size_t)e3.x * DIM + co);
        #pragma unroll
        for (int q = 0; q < 4; q++) {
            uint4 v = (q == 0) ? v0 : (q == 1) ? v1 : (q == 2) ? v2 : v3;
            float w = __uint_as_float((q == 0 ? e0 : q == 1 ? e1 : q == 2 ? e2 : e3).y);
            float2 f0 = __half22float2(*(__half2*)&v.x);
            float2 f1 = __half22float2(*(__half2*)&v.y);
            float2 f2 = __half22float2(*(__half2*)&v.z);
            float2 f3 = __half22float2(*(__half2*)&v.w);
            acc[0] = fmaf(w, f0.x, acc[0]); acc[1] = fmaf(w, f0.y, acc[1]);
            acc[2] = fmaf(w, f1.x, acc[2]); acc[3] = fmaf(w, f1.y, acc[3]);
            acc[4] = fmaf(w, f2.x, acc[4]); acc[5] = fmaf(w, f2.y, acc[5]);
            acc[6] = fmaf(w, f3.x, acc[6]); acc[7] = fmaf(w, f3.y, acc[7]);
        }
    }
    for (; i < cnt; i++) {
        uint2 e = sp[warp][i];
        float w = __uint_as_float(e.y);
        uint4 v = *(const uint4*)(g_y + (size_t)e.x * DIM + co);
        float2 f0 = __half22float2(*(__half2*)&v.x);
        float2 f1 = __half22float2(*(__half2*)&v.y);
        float2 f2 = __half22float2(*(__half2*)&v.z);
        float2 f3 = __half22float2(*(__half2*)&v.w);
        acc[0] = fmaf(w, f0.x, acc[0]); acc[1] = fmaf(w, f0.y, acc[1]);
        acc[2] = fmaf(w, f1.x, acc[2]); acc[3] = fmaf(w, f1.y, acc[3]);
        acc[4] = fmaf(w, f2.x, acc[4]); acc[5] = fmaf(w, f2.y, acc[5]);
        acc[6] = fmaf(w, f3.x, acc[6]); acc[7] = fmaf(w, f3.y, acc[7]);
    }

    float4 o0, o1;
    o0.x = fmaxf(acc[0], 0.f); o0.y = fmaxf(acc[1], 0.f);
    o0.z = fmaxf(acc[2], 0.f); o0.w = fmaxf(acc[3], 0.f);
    o1.x = fmaxf(acc[4], 0.f); o1.y = fmaxf(acc[5], 0.f);
    o1.z = fmaxf(acc[6], 0.f); o1.w = fmaxf(acc[7], 0.f);
    float* orow = out + (size_t)node * DIM + co;
    *(float4*)(orow + 0) = o0;
    *(float4*)(orow + 4) = o1;
}

// ---------------- host-side streams/events for fork-join (created once, no device mem) ----
namespace {
struct LaunchCtx {
    cudaStream_t s1, s2;
    cudaEvent_t e0, e1, e2;
    LaunchCtx() {
        cudaStreamCreateWithFlags(&s1, cudaStreamNonBlocking);
        cudaStreamCreateWithFlags(&s2, cudaStreamNonBlocking);
        cudaEventCreateWithFlags(&e0, cudaEventDisableTiming);
        cudaEventCreateWithFlags(&e1, cudaEventDisableTiming);
        cudaEventCreateWithFlags(&e2, cudaEventDisableTiming);
    }
};
LaunchCtx g_ctx;
}

extern "C" void kernel_launch(void* const* d_in, const int* in_sizes, int n_in,
                              void* d_out, int out_size) {
    const float* x    = (const float*)d_in[0];   // [N_NODES, 256]
    const int*   erow = (const int*)  d_in[1];   // [E]
    const int*   ecol = (const int*)  d_in[2];   // [E]
    const float* ev   = (const float*)d_in[3];   // [E]
    const float* W    = (const float*)d_in[4];   // [256, 256]
    float* out = (float*)d_out;                  // [N_NODES, 256]

    // fork from the (capturing) default stream
    cudaEventRecord(g_ctx.e0, 0);
    cudaStreamWaitEvent(g_ctx.s1, g_ctx.e0, 0);
    cudaStreamWaitEvent(g_ctx.s2, g_ctx.e0, 0);

    // chain 1: scatter
    zero_counts_kernel<<<(N_NODES + 255) / 256, 256, 0, g_ctx.s1>>>();
    scatter_kernel<<<NSCAT_BLKS, 256, 0, g_ctx.s1>>>(erow, ecol, ev);

    // chain 2: GEMM
    conv_xw_kernel<<<(M_PAD * 64 + 255) / 256, 256, 0, g_ctx.s2>>>(x, W);
    gemm_kernel<<<NGEMM_BLKS, 256, 0, g_ctx.s2>>>();

    // join
    cudaEventRecord(g_ctx.e1, g_ctx.s1);
    cudaEventRecord(g_ctx.e2, g_ctx.s2);
    cudaStreamWaitEvent(0, g_ctx.e1, 0);
    cudaStreamWaitEvent(0, g_ctx.e2, 0);

    aggregate_relu_kernel<<<N_NODES / 8, 256>>>(out);
}

// round 10
// speedup vs baseline: 1.6291x; 1.0156x over previous
#include <cuda_runtime.h>
#include <cuda_fp16.h>
#include <cstdint>

#define N_NODES 50000
#define N_EDGES 1600000
#define DIM 256
#define M_PAD 50048              // 391 * 128
#define BUCKET_CAP 128

// ---- device scratch (no allocations allowed) ----
__device__ __half g_y[(size_t)M_PAD * DIM];         // y = x @ W^T  (fp16, 25.6 MB)
__device__ int   g_count[N_NODES];
__device__ uint2 g_bucket[(size_t)N_NODES * BUCKET_CAP];   // {col, val bits}
__device__ __half g_xh[(size_t)M_PAD * DIM];        // x in fp16, zero-padded
__device__ __half g_wh[256 * 256];                  // W in fp16

// ---------------- prep A: zero counts (scatter chain) ----------------
__global__ void zero_counts_kernel() {
    int i = blockIdx.x * blockDim.x + threadIdx.x;
    if (i < N_NODES) g_count[i] = 0;
}

// ---------------- prep B: convert x and W to fp16 (GEMM chain) ----------------
__global__ __launch_bounds__(256) void conv_xw_kernel(const float* __restrict__ x,
                                                      const float* __restrict__ W) {
    int idx = blockIdx.x * 256 + threadIdx.x;        // over M_PAD*64
    if (idx < 256 * 256) g_wh[idx] = __float2half_rn(W[idx]);
    if (idx >= M_PAD * 64) return;
    int row = idx >> 6;
    int c4 = (idx & 63) * 4;
    float4 f = make_float4(0.f, 0.f, 0.f, 0.f);
    if (row < N_NODES) f = *(const float4*)(x + (size_t)row * DIM + c4);
    __half2 h0 = __floats2half2_rn(f.x, f.y);
    __half2 h1 = __floats2half2_rn(f.z, f.w);
    uint2 v;
    v.x = *(uint32_t*)&h0;
    v.y = *(uint32_t*)&h1;
    *(uint2*)(g_xh + (size_t)row * DIM + c4) = v;
}

// ---------------- scatter: standalone, low-register, high-occupancy ----------------
__global__ __launch_bounds__(256) void scatter_kernel(const int*   __restrict__ erow,
                                                      const int*   __restrict__ ecol,
                                                      const float* __restrict__ eval) {
    int e = blockIdx.x * 256 + threadIdx.x;
    if (e < N_EDGES) {
        int r = erow[e];
        int c = ecol[e];              // issue all three loads before the atomic
        float v = eval[e];
        int pos = atomicAdd(&g_count[r], 1);
        if (pos < BUCKET_CAP) {
            uint2 p;
            p.x = (uint32_t)c;
            p.y = __float_as_uint(v);
            g_bucket[(size_t)r * BUCKET_CAP + pos] = p;
        }
    }
}

// ---------------- GEMM: y = x @ W^T, fp16 MMA, cp.async pipeline, ldmatrix frags ----------------
#define GBM 128
#define GBN 128
#define GBK 32
#define APAD 40   // fp16 elems per smem row (80 B) -> ldmatrix conflict-free (see analysis)
#define NGEMM_BLKS ((M_PAD / GBM) * (DIM / GBN))       // 391*2 = 782
#define NSCAT_BLKS ((N_EDGES + 255) / 256)             // 6250

__device__ __forceinline__ void mma16816f16(float* d, const uint32_t* a, const uint32_t* b) {
    asm volatile(
        "mma.sync.aligned.m16n8k16.row.col.f32.f16.f16.f32 "
        "{%0,%1,%2,%3}, {%4,%5,%6,%7}, {%8,%9}, {%0,%1,%2,%3};"
        : "+f"(d[0]), "+f"(d[1]), "+f"(d[2]), "+f"(d[3])
        : "r"(a[0]), "r"(a[1]), "r"(a[2]), "r"(a[3]), "r"(b[0]), "r"(b[1]));
}
__device__ __forceinline__ void ldmx4(uint32_t* r, uint32_t addr) {
    asm volatile("ldmatrix.sync.aligned.m8n8.x4.shared.b16 {%0,%1,%2,%3}, [%4];"
        : "=r"(r[0]), "=r"(r[1]), "=r"(r[2]), "=r"(r[3]) : "r"(addr));
}
__device__ __forceinline__ void cp16(void* smem_dst, const void* gsrc) {
    uint32_t d = (uint32_t)__cvta_generic_to_shared(smem_dst);
    asm volatile("cp.async.cg.shared.global [%0], [%1], 16;" :: "r"(d), "l"(gsrc));
}
#define CP_COMMIT() asm volatile("cp.async.commit_group;" ::: "memory")
#define CP_WAIT0()  asm volatile("cp.async.wait_group 0;" ::: "memory")

__global__ __launch_bounds__(256) void gemm_kernel() {
    __shared__ __align__(16) __half Ah[2][GBM][APAD];
    __shared__ __align__(16) __half Bh[2][GBN][APAD];

    const int bid = blockIdx.x;
    const int tid = threadIdx.x;
    const int warp = tid >> 5;
    const int lane = tid & 31;
    const int wm = warp >> 2;          // 0..1
    const int wn = warp & 3;           // 0..3
    const int g = lane >> 2;           // 0..7
    const int t = lane & 3;            // 0..3

    const size_t bm = (size_t)(bid >> 1) * GBM;
    const int bn = (bid & 1) * GBN;

    // cp.async indexing: 512 16B-chunks per tile, 2 per thread per tile
    const int r0 = tid >> 2,          s0 = tid & 3;
    const int r1 = (tid + 256) >> 2,  s1 = (tid + 256) & 3;

    auto copy_tile = [&](int st, int k0) {
        cp16(&Ah[st][r0][s0 * 8], g_xh + (bm + r0) * DIM + k0 + s0 * 8);
        cp16(&Ah[st][r1][s1 * 8], g_xh + (bm + r1) * DIM + k0 + s1 * 8);
        cp16(&Bh[st][r0][s0 * 8], g_wh + (size_t)(bn + r0) * DIM + k0 + s0 * 8);
        cp16(&Bh[st][r1][s1 * 8], g_wh + (size_t)(bn + r1) * DIM + k0 + s1 * 8);
    };

    // ldmatrix per-lane base addresses (bytes), per stage
    // A x4: lanes 0-7 rows 0-7 @k0 | 8-15 rows 8-15 @k0 | 16-23 rows 0-7 @k8 | 24-31 rows 8-15 @k8
    const uint32_t a_row = (uint32_t)(wm * 64 + (lane & 15));
    const uint32_t a_kof = (uint32_t)((lane >> 4) * 8);
    // B x4: lanes 0-7 n 0-7 @k0 | 8-15 n 0-7 @k8 | 16-23 n 8-15 @k0 | 24-31 n 8-15 @k8
    const uint32_t b_row = (uint32_t)(wn * 32 + (lane & 7) + ((lane >> 4) << 3));
    const uint32_t b_kof = (uint32_t)(((lane >> 3) & 1) * 8);
    uint32_t a_base[2], b_base[2];
    #pragma unroll
    for (int st = 0; st < 2; st++) {
        a_base[st] = (uint32_t)__cvta_generic_to_shared(&Ah[st][a_row][a_kof]);
        b_base[st] = (uint32_t)__cvta_generic_to_shared(&Bh[st][b_row][b_kof]);
    }

    float acc[4][4][4];
    #pragma unroll
    for (int i = 0; i < 4; i++)
        #pragma unroll
        for (int j = 0; j < 4; j++)
            #pragma unroll
            for (int r = 0; r < 4; r++) acc[i][j][r] = 0.f;

    copy_tile(0, 0);
    CP_COMMIT();

    #pragma unroll 1
    for (int it = 0; it < DIM / GBK; it++) {
        const int st = it & 1;
        CP_WAIT0();
        __syncthreads();
        if (it + 1 < DIM / GBK) {
            copy_tile(st ^ 1, (it + 1) * GBK);
            CP_COMMIT();
        }

        #pragma unroll
        for (int ks = 0; ks < 2; ks++) {
            const uint32_t koff = (uint32_t)(ks * 16 * 2);       // 16 halfs = 32 B
            uint32_t bf[2][4];                                    // [pair][4 regs] = 4 n-tiles
            ldmx4(bf[0], b_base[st] + 0 * 16 * APAD * 2 + koff);  // ni 0,1
            ldmx4(bf[1], b_base[st] + 1 * 16 * APAD * 2 + koff);  // ni 2,3
            #pragma unroll
            for (int mi = 0; mi < 4; mi++) {
                uint32_t af[4];
                ldmx4(af, a_base[st] + (uint32_t)(mi * 16 * APAD * 2) + koff);
                #pragma unroll
                for (int ni = 0; ni < 4; ni++) {
                    mma16816f16(acc[mi][ni], af, &bf[ni >> 1][(ni & 1) * 2]);
                }
            }
        }
    }

    // epilogue: write fp16 y
    #pragma unroll
    for (int mi = 0; mi < 4; mi++) {
        size_t rr0 = bm + wm * 64 + mi * 16 + g;
        size_t rr1 = rr0 + 8;
        #pragma unroll
        for (int ni = 0; ni < 4; ni++) {
            int c = bn + wn * 32 + ni * 8 + 2 * t;
            __half2 v0 = __floats2half2_rn(acc[mi][ni][0], acc[mi][ni][1]);
            __half2 v1 = __floats2half2_rn(acc[mi][ni][2], acc[mi][ni][3]);
            *(__half2*)(g_y + rr0 * DIM + c) = v0;
            *(__half2*)(g_y + rr1 * DIM + c) = v1;
        }
    }
}

// ---------------- aggregation: 1 warp per node, uint4 gathers, MLP=4 ----------------
__global__ __launch_bounds__(256) void aggregate_relu_kernel(float* __restrict__ out) {
    __shared__ uint2 sp[8][BUCKET_CAP];
    const int warp = threadIdx.x >> 5;
    const int lane = threadIdx.x & 31;
    const int node = blockIdx.x * 8 + warp;   // 6250 * 8 = 50000 exactly

    int cnt = g_count[node];
    if (cnt > BUCKET_CAP) cnt = BUCKET_CAP;

    const uint2* bkt = g_bucket + (size_t)node * BUCKET_CAP;
    for (int i = lane; i < cnt; i += 32) sp[warp][i] = bkt[i];
    __syncwarp();

    float acc[8];
    #pragma unroll
    for (int j = 0; j < 8; j++) acc[j] = 0.f;

    const int co = lane * 8;                  // fp16 feature offset for this lane (16 B)
    int i = 0;
    for (; i + 4 <= cnt; i += 4) {
        uint2 e0 = sp[warp][i + 0];
        uint2 e1 = sp[warp][i + 1];
        uint2 e2 = sp[warp][i + 2];
        uint2 e3 = sp[warp][i + 3];
        uint4 v0 = *(const uint4*)(g_y + (size_t)e0.x * DIM + co);
        uint4 v1 = *(const uint4*)(g_y + (size_t)e1.x * DIM + co);
        uint4 v2 = *(const uint4*)(g_y + (size_t)e2.x * DIM + co);
        uint4 v3 = *(const uint4*)(g_y + (size_t)e3.x * DIM + co);
        #pragma unroll
        for (int q = 0; q < 4; q++) {
            uint4 v = (q == 0) ? v0 : (q == 1) ? v1 : (q == 2) ? v2 : v3;
            float w = __uint_as_float((q == 0 ? e0 : q == 1 ? e1 : q == 2 ? e2 : e3).y);
            float2 f0 = __half22float2(*(__half2*)&v.x);
            float2 f1 = __half22float2(*(__half2*)&v.y);
            float2 f2 = __half22float2(*(__half2*)&v.z);
            float2 f3 = __half22float2(*(__half2*)&v.w);
            acc[0] = fmaf(w, f0.x, acc[0]); acc[1] = fmaf(w, f0.y, acc[1]);
            acc[2] = fmaf(w, f1.x, acc[2]); acc[3] = fmaf(w, f1.y, acc[3]);
            acc[4] = fmaf(w, f2.x, acc[4]); acc[5] = fmaf(w, f2.y, acc[5]);
            acc[6] = fmaf(w, f3.x, acc[6]); acc[7] = fmaf(w, f3.y, acc[7]);
        }
    }
    for (; i < cnt; i++) {
        uint2 e = sp[warp][i];
        float w = __uint_as_float(e.y);
        uint4 v = *(const uint4*)(g_y + (size_t)e.x * DIM + co);
        float2 f0 = __half22float2(*(__half2*)&v.x);
        float2 f1 = __half22float2(*(__half2*)&v.y);
        float2 f2 = __half22float2(*(__half2*)&v.z);
        float2 f3 = __half22float2(*(__half2*)&v.w);
        acc[0] = fmaf(w, f0.x, acc[0]); acc[1] = fmaf(w, f0.y, acc[1]);
        acc[2] = fmaf(w, f1.x, acc[2]); acc[3] = fmaf(w, f1.y, acc[3]);
        acc[4] = fmaf(w, f2.x, acc[4]); acc[5] = fmaf(w, f2.y, acc[5]);
        acc[6] = fmaf(w, f3.x, acc[6]); acc[7] = fmaf(w, f3.y, acc[7]);
    }

    float4 o0, o1;
    o0.x = fmaxf(acc[0], 0.f); o0.y = fmaxf(acc[1], 0.f);
    o0.z = fmaxf(acc[2], 0.f); o0.w = fmaxf(acc[3], 0.f);
    o1.x = fmaxf(acc[4], 0.f); o1.y = fmaxf(acc[5], 0.f);
    o1.z = fmaxf(acc[6], 0.f); o1.w = fmaxf(acc[7], 0.f);
    float* orow = out + (size_t)node * DIM + co;
    *(float4*)(orow + 0) = o0;
    *(float4*)(orow + 4) = o1;
}

// ---------------- host-side streams/events for fork-join (created once, no device mem) ----
namespace {
struct LaunchCtx {
    cudaStream_t s1, s2;
    cudaEvent_t e0, e1, e2;
    LaunchCtx() {
        cudaStreamCreateWithFlags(&s1, cudaStreamNonBlocking);
        cudaStreamCreateWithFlags(&s2, cudaStreamNonBlocking);
        cudaEventCreateWithFlags(&e0, cudaEventDisableTiming);
        cudaEventCreateWithFlags(&e1, cudaEventDisableTiming);
        cudaEventCreateWithFlags(&e2, cudaEventDisableTiming);
    }
};
LaunchCtx g_ctx;
}

extern "C" void kernel_launch(void* const* d_in, const int* in_sizes, int n_in,
                              void* d_out, int out_size) {
    const float* x    = (const float*)d_in[0];   // [N_NODES, 256]
    const int*   erow = (const int*)  d_in[1];   // [E]
    const int*   ecol = (const int*)  d_in[2];   // [E]
    const float* ev   = (const float*)d_in[3];   // [E]
    const float* W    = (const float*)d_in[4];   // [256, 256]
    float* out = (float*)d_out;                  // [N_NODES, 256]

    // fork from the (capturing) default stream
    cudaEventRecord(g_ctx.e0, 0);
    cudaStreamWaitEvent(g_ctx.s1, g_ctx.e0, 0);
    cudaStreamWaitEvent(g_ctx.s2, g_ctx.e0, 0);

    // chain 1: scatter
    zero_counts_kernel<<<(N_NODES + 255) / 256, 256, 0, g_ctx.s1>>>();
    scatter_kernel<<<NSCAT_BLKS, 256, 0, g_ctx.s1>>>(erow, ecol, ev);

    // chain 2: GEMM
    conv_xw_kernel<<<(M_PAD * 64 + 255) / 256, 256, 0, g_ctx.s2>>>(x, W);
    gemm_kernel<<<NGEMM_BLKS, 256, 0, g_ctx.s2>>>();

    // join
    cudaEventRecord(g_ctx.e1, g_ctx.s1);
    cudaEventRecord(g_ctx.e2, g_ctx.s2);
    cudaStreamWaitEvent(0, g_ctx.e1, 0);
    cudaStreamWaitEvent(0, g_ctx.e2, 0);

    aggregate_relu_kernel<<<N_NODES / 8, 256>>>(out);
}

// round 11
// speedup vs baseline: 1.6812x; 1.0320x over previous
#include <cuda_runtime.h>
#include <cuda_fp16.h>
#include <cstdint>

#define N_NODES 50000
#define N_EDGES 1600000
#define DIM 256
#define M_PAD 50048              // 391 * 128
#define BUCKET_CAP 128

// ---- device scratch (no allocations allowed) ----
__device__ __half g_y[(size_t)M_PAD * DIM];         // y = x @ W^T  (fp16, 25.6 MB)
__device__ int   g_count[N_NODES];
__device__ uint2 g_bucket[(size_t)N_NODES * BUCKET_CAP];   // {col, val bits}
__device__ __half g_xh[(size_t)M_PAD * DIM];        // x in fp16, zero-padded
__device__ __half g_wh[256 * 256];                  // W in fp16

// ---------------- prep B: convert x and W to fp16 (GEMM chain) ----------------
__global__ __launch_bounds__(256) void conv_xw_kernel(const float* __restrict__ x,
                                                      const float* __restrict__ W) {
    int idx = blockIdx.x * 256 + threadIdx.x;        // over M_PAD*64
    if (idx < 256 * 256) g_wh[idx] = __float2half_rn(W[idx]);
    if (idx >= M_PAD * 64) return;
    int row = idx >> 6;
    int c4 = (idx & 63) * 4;
    float4 f = make_float4(0.f, 0.f, 0.f, 0.f);
    if (row < N_NODES) f = *(const float4*)(x + (size_t)row * DIM + c4);
    __half2 h0 = __floats2half2_rn(f.x, f.y);
    __half2 h1 = __floats2half2_rn(f.z, f.w);
    uint2 v;
    v.x = *(uint32_t*)&h0;
    v.y = *(uint32_t*)&h1;
    *(uint2*)(g_xh + (size_t)row * DIM + c4) = v;
}

// ---------------- scatter: standalone, low-register, high-occupancy ----------------
__global__ __launch_bounds__(256) void scatter_kernel(const int*   __restrict__ erow,
                                                      const int*   __restrict__ ecol,
                                                      const float* __restrict__ eval) {
    int e = blockIdx.x * 256 + threadIdx.x;
    if (e < N_EDGES) {
        int r = erow[e];
        int c = ecol[e];              // issue all three loads before the atomic
        float v = eval[e];
        int pos = atomicAdd(&g_count[r], 1);
        if (pos < BUCKET_CAP) {
            uint2 p;
            p.x = (uint32_t)c;
            p.y = __float_as_uint(v);
            g_bucket[(size_t)r * BUCKET_CAP + pos] = p;
        }
    }
}

// ---------------- GEMM: fp16 MMA, 3-stage cp.async pipeline, ldmatrix frags ----------------
#define GBM 128
#define GBN 128
#define GBK 32
#define APAD 40   // fp16 elems per smem row (80 B) -> conflict-free ldmatrix
#define NSTAGE 3
#define NGEMM_BLKS ((M_PAD / GBM) * (DIM / GBN))       // 391*2 = 782
#define NSCAT_BLKS ((N_EDGES + 255) / 256)             // 6250

__device__ __forceinline__ void mma16816f16(float* d, const uint32_t* a, const uint32_t* b) {
    asm volatile(
        "mma.sync.aligned.m16n8k16.row.col.f32.f16.f16.f32 "
        "{%0,%1,%2,%3}, {%4,%5,%6,%7}, {%8,%9}, {%0,%1,%2,%3};"
        : "+f"(d[0]), "+f"(d[1]), "+f"(d[2]), "+f"(d[3])
        : "r"(a[0]), "r"(a[1]), "r"(a[2]), "r"(a[3]), "r"(b[0]), "r"(b[1]));
}
__device__ __forceinline__ void ldmx4(uint32_t* r, uint32_t addr) {
    asm volatile("ldmatrix.sync.aligned.m8n8.x4.shared.b16 {%0,%1,%2,%3}, [%4];"
        : "=r"(r[0]), "=r"(r[1]), "=r"(r[2]), "=r"(r[3]) : "r"(addr));
}
__device__ __forceinline__ void cp16(void* smem_dst, const void* gsrc) {
    uint32_t d = (uint32_t)__cvta_generic_to_shared(smem_dst);
    asm volatile("cp.async.cg.shared.global [%0], [%1], 16;" :: "r"(d), "l"(gsrc));
}
#define CP_COMMIT() asm volatile("cp.async.commit_group;" ::: "memory")
#define CP_WAIT(n)  asm volatile("cp.async.wait_group %0;" :: "n"(n) : "memory")

__global__ __launch_bounds__(256) void gemm_kernel() {
    __shared__ __align__(16) __half Ah[NSTAGE][GBM][APAD];
    __shared__ __align__(16) __half Bh[NSTAGE][GBN][APAD];

    const int bid = blockIdx.x;
    const int tid = threadIdx.x;
    const int warp = tid >> 5;
    const int lane = tid & 31;
    const int wm = warp >> 2;          // 0..1
    const int wn = warp & 3;           // 0..3
    const int g = lane >> 2;           // 0..7
    const int t = lane & 3;            // 0..3

    const size_t bm = (size_t)(bid >> 1) * GBM;
    const int bn = (bid & 1) * GBN;

    // cp.async indexing: 512 16B-chunks per tile, 2 per thread per tile
    const int r0 = tid >> 2,          s0 = tid & 3;
    const int r1 = (tid + 256) >> 2,  s1 = (tid + 256) & 3;

    auto copy_tile = [&](int st, int k0) {
        cp16(&Ah[st][r0][s0 * 8], g_xh + (bm + r0) * DIM + k0 + s0 * 8);
        cp16(&Ah[st][r1][s1 * 8], g_xh + (bm + r1) * DIM + k0 + s1 * 8);
        cp16(&Bh[st][r0][s0 * 8], g_wh + (size_t)(bn + r0) * DIM + k0 + s0 * 8);
        cp16(&Bh[st][r1][s1 * 8], g_wh + (size_t)(bn + r1) * DIM + k0 + s1 * 8);
        CP_COMMIT();
    };

    // ldmatrix per-lane base addresses
    const uint32_t a_row = (uint32_t)(wm * 64 + (lane & 15));
    const uint32_t a_kof = (uint32_t)((lane >> 4) * 8);
    const uint32_t b_row = (uint32_t)(wn * 32 + (lane & 7) + ((lane >> 4) << 3));
    const uint32_t b_kof = (uint32_t)(((lane >> 3) & 1) * 8);
    uint32_t a_base[NSTAGE], b_base[NSTAGE];
    #pragma unroll
    for (int st = 0; st < NSTAGE; st++) {
        a_base[st] = (uint32_t)__cvta_generic_to_shared(&Ah[st][a_row][a_kof]);
        b_base[st] = (uint32_t)__cvta_generic_to_shared(&Bh[st][b_row][b_kof]);
    }

    float acc[4][4][4];
    #pragma unroll
    for (int i = 0; i < 4; i++)
        #pragma unroll
        for (int j = 0; j < 4; j++)
            #pragma unroll
            for (int r = 0; r < 4; r++) acc[i][j][r] = 0.f;

    copy_tile(0, 0);
    copy_tile(1, GBK);

    #pragma unroll
    for (int it = 0; it < DIM / GBK; it++) {
        const int st = it % NSTAGE;
        CP_WAIT(1);                      // stage st's copy complete (one younger may remain)
        __syncthreads();                 // all warps see stage st; frees stage (it-1)%NSTAGE
        if (it + 2 < DIM / GBK)
            copy_tile((it + 2) % NSTAGE, (it + 2) * GBK);

        #pragma unroll
        for (int ks = 0; ks < 2; ks++) {
            const uint32_t koff = (uint32_t)(ks * 16 * 2);       // 16 halfs = 32 B
            uint32_t bf[2][4];
            ldmx4(bf[0], b_base[st] + 0 * 16 * APAD * 2 + koff);  // ni 0,1
            ldmx4(bf[1], b_base[st] + 1 * 16 * APAD * 2 + koff);  // ni 2,3
            #pragma unroll
            for (int mi = 0; mi < 4; mi++) {
                uint32_t af[4];
                ldmx4(af, a_base[st] + (uint32_t)(mi * 16 * APAD * 2) + koff);
                #pragma unroll
                for (int ni = 0; ni < 4; ni++) {
                    mma16816f16(acc[mi][ni], af, &bf[ni >> 1][(ni & 1) * 2]);
                }
            }
        }
    }

    // epilogue: write fp16 y
    #pragma unroll
    for (int mi = 0; mi < 4; mi++) {
        size_t rr0 = bm + wm * 64 + mi * 16 + g;
        size_t rr1 = rr0 + 8;
        #pragma unroll
        for (int ni = 0; ni < 4; ni++) {
            int c = bn + wn * 32 + ni * 8 + 2 * t;
            __half2 v0 = __floats2half2_rn(acc[mi][ni][0], acc[mi][ni][1]);
            __half2 v1 = __floats2half2_rn(acc[mi][ni][2], acc[mi][ni][3]);
            *(__half2*)(g_y + rr0 * DIM + c) = v0;
            *(__half2*)(g_y + rr1 * DIM + c) = v1;
        }
    }
}

// ---------------- aggregation: 1 warp per node, uint4 gathers, MLP=4 ----------------
__global__ __launch_bounds__(256) void aggregate_relu_kernel(float* __restrict__ out) {
    __shared__ uint2 sp[8][BUCKET_CAP];
    const int warp = threadIdx.x >> 5;
    const int lane = threadIdx.x & 31;
    const int node = blockIdx.x * 8 + warp;   // 6250 * 8 = 50000 exactly

    int cnt = g_count[node];
    if (cnt > BUCKET_CAP) cnt = BUCKET_CAP;

    const uint2* bkt = g_bucket + (size_t)node * BUCKET_CAP;
    for (int i = lane; i < cnt; i += 32) sp[warp][i] = bkt[i];
    __syncwarp();

    float acc[8];
    #pragma unroll
    for (int j = 0; j < 8; j++) acc[j] = 0.f;

    const int co = lane * 8;                  // fp16 feature offset for this lane (16 B)
    int i = 0;
    for (; i + 4 <= cnt; i += 4) {
        uint2 e0 = sp[warp][i + 0];
        uint2 e1 = sp[warp][i + 1];
        uint2 e2 = sp[warp][i + 2];
        uint2 e3 = sp[warp][i + 3];
        uint4 v0 = *(const uint4*)(g_y + (size_t)e0.x * DIM + co);
        uint4 v1 = *(const uint4*)(g_y + (size_t)e1.x * DIM + co);
        uint4 v2 = *(const uint4*)(g_y + (size_t)e2.x * DIM + co);
        uint4 v3 = *(const uint4*)(g_y + (size_t)e3.x * DIM + co);
        #pragma unroll
        for (int q = 0; q < 4; q++) {
            uint4 v = (q == 0) ? v0 : (q == 1) ? v1 : (q == 2) ? v2 : v3;
            float w = __uint_as_float((q == 0 ? e0 : q == 1 ? e1 : q == 2 ? e2 : e3).y);
            float2 f0 = __half22float2(*(__half2*)&v.x);
            float2 f1 = __half22float2(*(__half2*)&v.y);
            float2 f2 = __half22float2(*(__half2*)&v.z);
            float2 f3 = __half22float2(*(__half2*)&v.w);
            acc[0] = fmaf(w, f0.x, acc[0]); acc[1] = fmaf(w, f0.y, acc[1]);
            acc[2] = fmaf(w, f1.x, acc[2]); acc[3] = fmaf(w, f1.y, acc[3]);
            acc[4] = fmaf(w, f2.x, acc[4]); acc[5] = fmaf(w, f2.y, acc[5]);
            acc[6] = fmaf(w, f3.x, acc[6]); acc[7] = fmaf(w, f3.y, acc[7]);
        }
    }
    for (; i < cnt; i++) {
        uint2 e = sp[warp][i];
        float w = __uint_as_float(e.y);
        uint4 v = *(const uint4*)(g_y + (size_t)e.x * DIM + co);
        float2 f0 = __half22float2(*(__half2*)&v.x);
        float2 f1 = __half22float2(*(__half2*)&v.y);
        float2 f2 = __half22float2(*(__half2*)&v.z);
        float2 f3 = __half22float2(*(__half2*)&v.w);
        acc[0] = fmaf(w, f0.x, acc[0]); acc[1] = fmaf(w, f0.y, acc[1]);
        acc[2] = fmaf(w, f1.x, acc[2]); acc[3] = fmaf(w, f1.y, acc[3]);
        acc[4] = fmaf(w, f2.x, acc[4]); acc[5] = fmaf(w, f2.y, acc[5]);
        acc[6] = fmaf(w, f3.x, acc[6]); acc[7] = fmaf(w, f3.y, acc[7]);
    }

    float4 o0, o1;
    o0.x = fmaxf(acc[0], 0.f); o0.y = fmaxf(acc[1], 0.f);
    o0.z = fmaxf(acc[2], 0.f); o0.w = fmaxf(acc[3], 0.f);
    o1.x = fmaxf(acc[4], 0.f); o1.y = fmaxf(acc[5], 0.f);
    o1.z = fmaxf(acc[6], 0.f); o1.w = fmaxf(acc[7], 0.f);
    float* orow = out + (size_t)node * DIM + co;
    *(float4*)(orow + 0) = o0;
    *(float4*)(orow + 4) = o1;
}

// ---------------- host-side streams/events (created once, no device mem) ----------------
namespace {
struct LaunchCtx {
    cudaStream_t s1, s2;
    cudaEvent_t e0, e1, e2;
    void* count_ptr;
    LaunchCtx() {
        cudaStreamCreateWithFlags(&s1, cudaStreamNonBlocking);
        cudaStreamCreateWithFlags(&s2, cudaStreamNonBlocking);
        cudaEventCreateWithFlags(&e0, cudaEventDisableTiming);
        cudaEventCreateWithFlags(&e1, cudaEventDisableTiming);
        cudaEventCreateWithFlags(&e2, cudaEventDisableTiming);
        cudaGetSymbolAddress(&count_ptr, g_count);
    }
};
LaunchCtx g_ctx;
}

extern "C" void kernel_launch(void* const* d_in, const int* in_sizes, int n_in,
                              void* d_out, int out_size) {
    const float* x    = (const float*)d_in[0];   // [N_NODES, 256]
    const int*   erow = (const int*)  d_in[1];   // [E]
    const int*   ecol = (const int*)  d_in[2];   // [E]
    const float* ev   = (const float*)d_in[3];   // [E]
    const float* W    = (const float*)d_in[4];   // [256, 256]
    float* out = (float*)d_out;                  // [N_NODES, 256]

    // fork from the (capturing) default stream
    cudaEventRecord(g_ctx.e0, 0);
    cudaStreamWaitEvent(g_ctx.s1, g_ctx.e0, 0);
    cudaStreamWaitEvent(g_ctx.s2, g_ctx.e0, 0);

    // chain 1: scatter
    cudaMemsetAsync(g_ctx.count_ptr, 0, N_NODES * sizeof(int), g_ctx.s1);
    scatter_kernel<<<NSCAT_BLKS, 256, 0, g_ctx.s1>>>(erow, ecol, ev);

    // chain 2: GEMM
    conv_xw_kernel<<<(M_PAD * 64 + 255) / 256, 256, 0, g_ctx.s2>>>(x, W);
    gemm_kernel<<<NGEMM_BLKS, 256, 0, g_ctx.s2>>>();

    // join
    cudaEventRecord(g_ctx.e1, g_ctx.s1);
    cudaEventRecord(g_ctx.e2, g_ctx.s2);
    cudaStreamWaitEvent(0, g_ctx.e1, 0);
    cudaStreamWaitEvent(0, g_ctx.e2, 0);

    aggregate_relu_kernel<<<N_NODES / 8, 256>>>(out);
}

// round 12
// speedup vs baseline: 1.7044x; 1.0138x over previous
#include <cuda_runtime.h>
#include <cuda_fp16.h>
#include <cstdint>

#define N_NODES 50000
#define N_EDGES 1600000
#define DIM 256
#define M_PAD 50048              // 391 * 128
#define BUCKET_CAP 128

// ---- device scratch (no allocations allowed) ----
__device__ __half g_y[(size_t)M_PAD * DIM];         // y = x @ W^T  (fp16, 25.6 MB)
__device__ int   g_count[N_NODES];
__device__ uint2 g_bucket[(size_t)N_NODES * BUCKET_CAP];   // {col, val bits}
__device__ __half g_xh[(size_t)M_PAD * DIM];        // x in fp16, zero-padded
__device__ __half g_wh[256 * 256];                  // W in fp16

// ---------------- prep B: convert x and W to fp16 (GEMM chain) ----------------
__global__ __launch_bounds__(256) void conv_xw_kernel(const float* __restrict__ x,
                                                      const float* __restrict__ W) {
    int idx = blockIdx.x * 256 + threadIdx.x;        // over M_PAD*64
    if (idx < 256 * 256) g_wh[idx] = __float2half_rn(W[idx]);
    if (idx >= M_PAD * 64) return;
    int row = idx >> 6;
    int c4 = (idx & 63) * 4;
    float4 f = make_float4(0.f, 0.f, 0.f, 0.f);
    if (row < N_NODES) f = *(const float4*)(x + (size_t)row * DIM + c4);
    __half2 h0 = __floats2half2_rn(f.x, f.y);
    __half2 h1 = __floats2half2_rn(f.z, f.w);
    uint2 v;
    v.x = *(uint32_t*)&h0;
    v.y = *(uint32_t*)&h1;
    *(uint2*)(g_xh + (size_t)row * DIM + c4) = v;
}

// ---------------- scatter: standalone, low-register, high-occupancy ----------------
__global__ __launch_bounds__(256) void scatter_kernel(const int*   __restrict__ erow,
                                                      const int*   __restrict__ ecol,
                                                      const float* __restrict__ eval) {
    int e = blockIdx.x * 256 + threadIdx.x;
    if (e < N_EDGES) {
        int r = erow[e];
        int c = ecol[e];              // issue all three loads before the atomic
        float v = eval[e];
        int pos = atomicAdd(&g_count[r], 1);
        if (pos < BUCKET_CAP) {
            uint2 p;
            p.x = (uint32_t)c;
            p.y = __float_as_uint(v);
            g_bucket[(size_t)r * BUCKET_CAP + pos] = p;
        }
    }
}

// ---------------- GEMM: fp16 MMA, 4-stage cp.async pipeline, batched ldmatrix ----------------
#define GBM 128
#define GBN 128
#define GBK 32
#define APAD 40   // fp16 elems per smem row (80 B) -> conflict-free ldmatrix
#define NSTAGE 4
#define KITERS (DIM / GBK)                             // 8
#define NGEMM_BLKS ((M_PAD / GBM) * (DIM / GBN))       // 391*2 = 782
#define NSCAT_BLKS ((N_EDGES + 255) / 256)             // 6250

__device__ __forceinline__ void mma16816f16(float* d, const uint32_t* a, const uint32_t* b) {
    asm volatile(
        "mma.sync.aligned.m16n8k16.row.col.f32.f16.f16.f32 "
        "{%0,%1,%2,%3}, {%4,%5,%6,%7}, {%8,%9}, {%0,%1,%2,%3};"
        : "+f"(d[0]), "+f"(d[1]), "+f"(d[2]), "+f"(d[3])
        : "r"(a[0]), "r"(a[1]), "r"(a[2]), "r"(a[3]), "r"(b[0]), "r"(b[1]));
}
__device__ __forceinline__ void ldmx4(uint32_t* r, uint32_t addr) {
    asm volatile("ldmatrix.sync.aligned.m8n8.x4.shared.b16 {%0,%1,%2,%3}, [%4];"
        : "=r"(r[0]), "=r"(r[1]), "=r"(r[2]), "=r"(r[3]) : "r"(addr));
}
__device__ __forceinline__ void cp16(void* smem_dst, const void* gsrc) {
    uint32_t d = (uint32_t)__cvta_generic_to_shared(smem_dst);
    asm volatile("cp.async.cg.shared.global [%0], [%1], 16;" :: "r"(d), "l"(gsrc));
}
#define CP_COMMIT() asm volatile("cp.async.commit_group;" ::: "memory")
#define CP_WAIT(n)  asm volatile("cp.async.wait_group %0;" :: "n"(n) : "memory")

__global__ __launch_bounds__(256) void gemm_kernel() {
    __shared__ __align__(16) __half Ah[NSTAGE][GBM][APAD];
    __shared__ __align__(16) __half Bh[NSTAGE][GBN][APAD];

    const int bid = blockIdx.x;
    const int tid = threadIdx.x;
    const int warp = tid >> 5;
    const int lane = tid & 31;
    const int wm = warp >> 2;          // 0..1
    const int wn = warp & 3;           // 0..3
    const int g = lane >> 2;           // 0..7
    const int t = lane & 3;            // 0..3

    const size_t bm = (size_t)(bid >> 1) * GBM;
    const int bn = (bid & 1) * GBN;

    // cp.async indexing: 512 16B-chunks per tile, 2 per thread per tile
    const int r0 = tid >> 2,          s0 = tid & 3;
    const int r1 = (tid + 256) >> 2,  s1 = (tid + 256) & 3;

    auto copy_tile = [&](int st, int k0) {
        cp16(&Ah[st][r0][s0 * 8], g_xh + (bm + r0) * DIM + k0 + s0 * 8);
        cp16(&Ah[st][r1][s1 * 8], g_xh + (bm + r1) * DIM + k0 + s1 * 8);
        cp16(&Bh[st][r0][s0 * 8], g_wh + (size_t)(bn + r0) * DIM + k0 + s0 * 8);
        cp16(&Bh[st][r1][s1 * 8], g_wh + (size_t)(bn + r1) * DIM + k0 + s1 * 8);
        CP_COMMIT();
    };

    // ldmatrix per-lane base addresses
    const uint32_t a_row = (uint32_t)(wm * 64 + (lane & 15));
    const uint32_t a_kof = (uint32_t)((lane >> 4) * 8);
    const uint32_t b_row = (uint32_t)(wn * 32 + (lane & 7) + ((lane >> 4) << 3));
    const uint32_t b_kof = (uint32_t)(((lane >> 3) & 1) * 8);
    uint32_t a_base[NSTAGE], b_base[NSTAGE];
    #pragma unroll
    for (int st = 0; st < NSTAGE; st++) {
        a_base[st] = (uint32_t)__cvta_generic_to_shared(&Ah[st][a_row][a_kof]);
        b_base[st] = (uint32_t)__cvta_generic_to_shared(&Bh[st][b_row][b_kof]);
    }

    float acc[4][4][4];
    #pragma unroll
    for (int i = 0; i < 4; i++)
        #pragma unroll
        for (int j = 0; j < 4; j++)
            #pragma unroll
            for (int r = 0; r < 4; r++) acc[i][j][r] = 0.f;

    copy_tile(0, 0);
    copy_tile(1, 1 * GBK);
    copy_tile(2, 2 * GBK);

    #pragma unroll
    for (int it = 0; it < KITERS; it++) {
        const int st = it & 3;
        // need stage `it` complete; youngest committed = min(it+2, KITERS-1)
        if (it + 1 >= KITERS)      CP_WAIT(0);
        else if (it + 2 >= KITERS) CP_WAIT(1);
        else                       CP_WAIT(2);
        __syncthreads();                 // frees stage (it-1)%4 = (it+3)%4 for the copy below
        if (it + 3 < KITERS)
            copy_tile((it + 3) & 3, (it + 3) * GBK);

        #pragma unroll
        for (int ks = 0; ks < 2; ks++) {
            const uint32_t koff = (uint32_t)(ks * 16 * 2);       // 16 halfs = 32 B
            // batch ALL fragment loads first, then a clean HMMA stretch
            uint32_t bf[2][4];
            uint32_t af[4][4];
            ldmx4(bf[0], b_base[st] + 0 * 16 * APAD * 2 + koff);  // ni 0,1
            ldmx4(bf[1], b_base[st] + 1 * 16 * APAD * 2 + koff);  // ni 2,3
            #pragma unroll
            for (int mi = 0; mi < 4; mi++)
                ldmx4(af[mi], a_base[st] + (uint32_t)(mi * 16 * APAD * 2) + koff);
            #pragma unroll
            for (int mi = 0; mi < 4; mi++)
                #pragma unroll
                for (int ni = 0; ni < 4; ni++)
                    mma16816f16(acc[mi][ni], af[mi], &bf[ni >> 1][(ni & 1) * 2]);
        }
    }

    // epilogue: write fp16 y
    #pragma unroll
    for (int mi = 0; mi < 4; mi++) {
        size_t rr0 = bm + wm * 64 + mi * 16 + g;
        size_t rr1 = rr0 + 8;
        #pragma unroll
        for (int ni = 0; ni < 4; ni++) {
            int c = bn + wn * 32 + ni * 8 + 2 * t;
            __half2 v0 = __floats2half2_rn(acc[mi][ni][0], acc[mi][ni][1]);
            __half2 v1 = __floats2half2_rn(acc[mi][ni][2], acc[mi][ni][3]);
            *(__half2*)(g_y + rr0 * DIM + c) = v0;
            *(__half2*)(g_y + rr1 * DIM + c) = v1;
        }
    }
}

// ---------------- aggregation: 1 warp per node, uint4 gathers, MLP=4 (at L2 floor) ----------------
__global__ __launch_bounds__(256) void aggregate_relu_kernel(float* __restrict__ out) {
    __shared__ uint2 sp[8][BUCKET_CAP];
    const int warp = threadIdx.x >> 5;
    const int lane = threadIdx.x & 31;
    const int node = blockIdx.x * 8 + warp;   // 6250 * 8 = 50000 exactly

    int cnt = g_count[node];
    if (cnt > BUCKET_CAP) cnt = BUCKET_CAP;

    const uint2* bkt = g_bucket + (size_t)node * BUCKET_CAP;
    for (int i = lane; i < cnt; i += 32) sp[warp][i] = bkt[i];
    __syncwarp();

    float acc[8];
    #pragma unroll
    for (int j = 0; j < 8; j++) acc[j] = 0.f;

    const int co = lane * 8;                  // fp16 feature offset for this lane (16 B)
    int i = 0;
    for (; i + 4 <= cnt; i += 4) {
        uint2 e0 = sp[warp][i + 0];
        uint2 e1 = sp[warp][i + 1];
        uint2 e2 = sp[warp][i + 2];
        uint2 e3 = sp[warp][i + 3];
        uint4 v0 = *(const uint4*)(g_y + (size_t)e0.x * DIM + co);
        uint4 v1 = *(const uint4*)(g_y + (size_t)e1.x * DIM + co);
        uint4 v2 = *(const uint4*)(g_y + (size_t)e2.x * DIM + co);
        uint4 v3 = *(const uint4*)(g_y + (size_t)e3.x * DIM + co);
        #pragma unroll
        for (int q = 0; q < 4; q++) {
            uint4 v = (q == 0) ? v0 : (q == 1) ? v1 : (q == 2) ? v2 : v3;
            float w = __uint_as_float((q == 0 ? e0 : q == 1 ? e1 : q == 2 ? e2 : e3).y);
            float2 f0 = __half22float2(*(__half2*)&v.x);
            float2 f1 = __half22float2(*(__half2*)&v.y);
            float2 f2 = __half22float2(*(__half2*)&v.z);
            float2 f3 = __half22float2(*(__half2*)&v.w);
            acc[0] = fmaf(w, f0.x, acc[0]); acc[1] = fmaf(w, f0.y, acc[1]);
            acc[2] = fmaf(w, f1.x, acc[2]); acc[3] = fmaf(w, f1.y, acc[3]);
            acc[4] = fmaf(w, f2.x, acc[4]); acc[5] = fmaf(w, f2.y, acc[5]);
            acc[6] = fmaf(w, f3.x, acc[6]); acc[7] = fmaf(w, f3.y, acc[7]);
        }
    }
    for (; i < cnt; i++) {
        uint2 e = sp[warp][i];
        float w = __uint_as_float(e.y);
        uint4 v = *(const uint4*)(g_y + (size_t)e.x * DIM + co);
        float2 f0 = __half22float2(*(__half2*)&v.x);
        float2 f1 = __half22float2(*(__half2*)&v.y);
        float2 f2 = __half22float2(*(__half2*)&v.z);
        float2 f3 = __half22float2(*(__half2*)&v.w);
        acc[0] = fmaf(w, f0.x, acc[0]); acc[1] = fmaf(w, f0.y, acc[1]);
        acc[2] = fmaf(w, f1.x, acc[2]); acc[3] = fmaf(w, f1.y, acc[3]);
        acc[4] = fmaf(w, f2.x, acc[4]); acc[5] = fmaf(w, f2.y, acc[5]);
        acc[6] = fmaf(w, f3.x, acc[6]); acc[7] = fmaf(w, f3.y, acc[7]);
    }

    float4 o0, o1;
    o0.x = fmaxf(acc[0], 0.f); o0.y = fmaxf(acc[1], 0.f);
    o0.z = fmaxf(acc[2], 0.f); o0.w = fmaxf(acc[3], 0.f);
    o1.x = fmaxf(acc[4], 0.f); o1.y = fmaxf(acc[5], 0.f);
    o1.z = fmaxf(acc[6], 0.f); o1.w = fmaxf(acc[7], 0.f);
    float* orow = out + (size_t)node * DIM + co;
    *(float4*)(orow + 0) = o0;
    *(float4*)(orow + 4) = o1;
}

// ---------------- host-side streams/events (created once, no device mem) ----------------
namespace {
struct LaunchCtx {
    cudaStream_t s1, s2;
    cudaEvent_t e0, e1, e2;
    void* count_ptr;
    LaunchCtx() {
        cudaStreamCreateWithFlags(&s1, cudaStreamNonBlocking);
        cudaStreamCreateWithFlags(&s2, cudaStreamNonBlocking);
        cudaEventCreateWithFlags(&e0, cudaEventDisableTiming);
        cudaEventCreateWithFlags(&e1, cudaEventDisableTiming);
        cudaEventCreateWithFlags(&e2, cudaEventDisableTiming);
        cudaGetSymbolAddress(&count_ptr, g_count);
    }
};
LaunchCtx g_ctx;
}

extern "C" void kernel_launch(void* const* d_in, const int* in_sizes, int n_in,
                              void* d_out, int out_size) {
    const float* x    = (const float*)d_in[0];   // [N_NODES, 256]
    const int*   erow = (const int*)  d_in[1];   // [E]
    const int*   ecol = (const int*)  d_in[2];   // [E]
    const float* ev   = (const float*)d_in[3];   // [E]
    const float* W    = (const float*)d_in[4];   // [256, 256]
    float* out = (float*)d_out;                  // [N_NODES, 256]

    // fork from the (capturing) default stream
    cudaEventRecord(g_ctx.e0, 0);
    cudaStreamWaitEvent(g_ctx.s1, g_ctx.e0, 0);
    cudaStreamWaitEvent(g_ctx.s2, g_ctx.e0, 0);

    // chain 2 first: GEMM is the longer chain
    conv_xw_kernel<<<(M_PAD * 64 + 255) / 256, 256, 0, g_ctx.s2>>>(x, W);
    gemm_kernel<<<NGEMM_BLKS, 256, 0, g_ctx.s2>>>();

    // chain 1: scatter
    cudaMemsetAsync(g_ctx.count_ptr, 0, N_NODES * sizeof(int), g_ctx.s1);
    scatter_kernel<<<NSCAT_BLKS, 256, 0, g_ctx.s1>>>(erow, ecol, ev);

    // join
    cudaEventRecord(g_ctx.e1, g_ctx.s1);
    cudaEventRecord(g_ctx.e2, g_ctx.s2);
    cudaStreamWaitEvent(0, g_ctx.e1, 0);
    cudaStreamWaitEvent(0, g_ctx.e2, 0);

    aggregate_relu_kernel<<<N_NODES / 8, 256>>>(out);
}

// round 14
// speedup vs baseline: 1.7354x; 1.0182x over previous
#include <cuda_runtime.h>
#include <cuda_fp16.h>
#include <cstdint>

#define N_NODES 50000
#define N_EDGES 1600000
#define DIM 256
#define M_PAD 50048              // 391 * 128
#define BUCKET_CAP 128

// ---- device scratch (no allocations allowed) ----
__device__ __half g_y[(size_t)M_PAD * DIM];         // y = x @ W^T  (fp16, 25.6 MB)
__device__ int   g_count[N_NODES];
__device__ uint2 g_bucket[(size_t)N_NODES * BUCKET_CAP];   // {col, val bits}
__device__ __half g_xh[(size_t)M_PAD * DIM];        // x in fp16, zero-padded
__device__ __half g_wh[256 * 256];                  // W in fp16

// ---------------- prep B: convert x and W to fp16 (GEMM chain) ----------------
__global__ __launch_bounds__(256) void conv_xw_kernel(const float* __restrict__ x,
                                                      const float* __restrict__ W) {
    int idx = blockIdx.x * 256 + threadIdx.x;        // over M_PAD*64
    if (idx < 256 * 256) g_wh[idx] = __float2half_rn(W[idx]);
    if (idx >= M_PAD * 64) return;
    int row = idx >> 6;
    int c4 = (idx & 63) * 4;
    float4 f = make_float4(0.f, 0.f, 0.f, 0.f);
    if (row < N_NODES) f = *(const float4*)(x + (size_t)row * DIM + c4);
    __half2 h0 = __floats2half2_rn(f.x, f.y);
    __half2 h1 = __floats2half2_rn(f.z, f.w);
    uint2 v;
    v.x = *(uint32_t*)&h0;
    v.y = *(uint32_t*)&h1;
    *(uint2*)(g_xh + (size_t)row * DIM + c4) = v;
}

// ---------------- scatter: standalone, low-register, high-occupancy ----------------
__global__ __launch_bounds__(256) void scatter_kernel(const int*   __restrict__ erow,
                                                      const int*   __restrict__ ecol,
                                                      const float* __restrict__ eval) {
    int e = blockIdx.x * 256 + threadIdx.x;
    if (e < N_EDGES) {
        int r = erow[e];
        int c = ecol[e];              // issue all three loads before the atomic
        float v = eval[e];
        int pos = atomicAdd(&g_count[r], 1);
        if (pos < BUCKET_CAP) {
            uint2 p;
            p.x = (uint32_t)c;
            p.y = __float_as_uint(v);
            g_bucket[(size_t)r * BUCKET_CAP + pos] = p;
        }
    }
}

// ---------------- GEMM: fp16 MMA, GBK=64, 3-stage cp.async pipeline (dynamic smem) ------
#define GBM 128
#define GBN 128
#define GBK 64
#define KPAD 72   // halfs per smem row (144 B) -> ldmatrix rows hit banks {0,4,..,28}: conflict-free
#define NSTAGE 3
#define STAGE_HALFS (GBM * KPAD)                       // 9216 halfs = 18 KB
#define GEMM_SMEM (NSTAGE * 2 * STAGE_HALFS * 2)       // 110592 B
#define KITERS (DIM / GBK)                             // 4
#define NGEMM_BLKS ((M_PAD / GBM) * (DIM / GBN))       // 391*2 = 782
#define NSCAT_BLKS ((N_EDGES + 255) / 256)             // 6250

__device__ __forceinline__ void mma16816f16(float* d, const uint32_t* a, const uint32_t* b) {
    asm volatile(
        "mma.sync.aligned.m16n8k16.row.col.f32.f16.f16.f32 "
        "{%0,%1,%2,%3}, {%4,%5,%6,%7}, {%8,%9}, {%0,%1,%2,%3};"
        : "+f"(d[0]), "+f"(d[1]), "+f"(d[2]), "+f"(d[3])
        : "r"(a[0]), "r"(a[1]), "r"(a[2]), "r"(a[3]), "r"(b[0]), "r"(b[1]));
}
__device__ __forceinline__ void ldmx4(uint32_t* r, uint32_t addr) {
    asm volatile("ldmatrix.sync.aligned.m8n8.x4.shared.b16 {%0,%1,%2,%3}, [%4];"
        : "=r"(r[0]), "=r"(r[1]), "=r"(r[2]), "=r"(r[3]) : "r"(addr));
}
__device__ __forceinline__ void cp16(uint32_t smem_dst, const void* gsrc) {
    asm volatile("cp.async.cg.shared.global [%0], [%1], 16;" :: "r"(smem_dst), "l"(gsrc));
}
#define CP_COMMIT() asm volatile("cp.async.commit_group;" ::: "memory")
#define CP_WAIT(n)  asm volatile("cp.async.wait_group %0;" :: "n"(n) : "memory")

__global__ __launch_bounds__(256) void gemm_kernel() {
    extern __shared__ __align__(16) __half sm[];
    // layout: A stages [0..NSTAGE), then B stages
    const uint32_t sm_base = (uint32_t)__cvta_generic_to_shared(sm);

    const int bid = blockIdx.x;
    const int tid = threadIdx.x;
    const int warp = tid >> 5;
    const int lane = tid & 31;
    const int wm = warp >> 2;          // 0..1
    const int wn = warp & 3;           // 0..3
    const int g = lane >> 2;           // 0..7
    const int t = lane & 3;            // 0..3

    const size_t bm = (size_t)(bid >> 1) * GBM;
    const int bn = (bid & 1) * GBN;

    // cp.async indexing: 1024 16B-chunks per tile, 4 per thread per tile
    // chunk c: row = c>>3, seg = c&7 (8 halfs each)
    auto copy_tile = [&](int st, int k0) {
        const uint32_t a_st = sm_base + (uint32_t)(st * STAGE_HALFS * 2);
        const uint32_t b_st = sm_base + (uint32_t)((NSTAGE + st) * STAGE_HALFS * 2);
        #pragma unroll
        for (int p = 0; p < 4; p++) {
            int c = tid + p * 256;
            int row = c >> 3, seg = c & 7;
            cp16(a_st + (uint32_t)(row * KPAD + seg * 8) * 2,
                 g_xh + (bm + row) * DIM + k0 + seg * 8);
            cp16(b_st + (uint32_t)(row * KPAD + seg * 8) * 2,
                 g_wh + (size_t)(bn + row) * DIM + k0 + seg * 8);
        }
        CP_COMMIT();
    };

    // ldmatrix per-lane base offsets (within a stage, in bytes)
    const uint32_t a_frag_off = (uint32_t)((wm * 64 + (lane & 15)) * KPAD + (lane >> 4) * 8) * 2;
    const uint32_t b_frag_off = (uint32_t)((wn * 32 + (lane & 7) + ((lane >> 4) << 3)) * KPAD
                                           + ((lane >> 3) & 1) * 8) * 2;

    float acc[4][4][4];
    #pragma unroll
    for (int i = 0; i < 4; i++)
        #pragma unroll
        for (int j = 0; j < 4; j++)
            #pragma unroll
            for (int r = 0; r < 4; r++) acc[i][j][r] = 0.f;

    copy_tile(0, 0);
    copy_tile(1, 1 * GBK);

    #pragma unroll
    for (int it = 0; it < KITERS; it++) {
        const int st = it % NSTAGE;
        if (it + 1 >= KITERS) CP_WAIT(0);     // last iter: everything must be done
        else                  CP_WAIT(1);     // one younger group may remain in flight
        __syncthreads();                      // frees stage (it+2)%3 = (it-1)%3
        if (it + 2 < KITERS)
            copy_tile((it + 2) % NSTAGE, (it + 2) * GBK);

        const uint32_t a_base = sm_base + (uint32_t)(st * STAGE_HALFS * 2) + a_frag_off;
        const uint32_t b_base = sm_base + (uint32_t)((NSTAGE + st) * STAGE_HALFS * 2) + b_frag_off;

        #pragma unroll
        for (int ks = 0; ks < 4; ks++) {
            const uint32_t koff = (uint32_t)(ks * 16 * 2);       // 16 halfs = 32 B
            uint32_t bf[2][4];
            uint32_t af[4][4];
            ldmx4(bf[0], b_base + 0 * 16 * KPAD * 2 + koff);      // ni 0,1
            ldmx4(bf[1], b_base + 1 * 16 * KPAD * 2 + koff);      // ni 2,3
            #pragma unroll
            for (int mi = 0; mi < 4; mi++)
                ldmx4(af[mi], a_base + (uint32_t)(mi * 16 * KPAD * 2) + koff);
            #pragma unroll
            for (int mi = 0; mi < 4; mi++)
                #pragma unroll
                for (int ni = 0; ni < 4; ni++)
                    mma16816f16(acc[mi][ni], af[mi], &bf[ni >> 1][(ni & 1) * 2]);
        }
    }

    // epilogue: write fp16 y
    #pragma unroll
    for (int mi = 0; mi < 4; mi++) {
        size_t rr0 = bm + wm * 64 + mi * 16 + g;
        size_t rr1 = rr0 + 8;
        #pragma unroll
        for (int ni = 0; ni < 4; ni++) {
            int c = bn + wn * 32 + ni * 8 + 2 * t;
            __half2 v0 = __floats2half2_rn(acc[mi][ni][0], acc[mi][ni][1]);
            __half2 v1 = __floats2half2_rn(acc[mi][ni][2], acc[mi][ni][3]);
            *(__half2*)(g_y + rr0 * DIM + c) = v0;
            *(__half2*)(g_y + rr1 * DIM + c) = v1;
        }
    }
}

// ---------------- aggregation: 1 warp per node, uint4 gathers, MLP=4 ----------------
__global__ __launch_bounds__(256) void aggregate_relu_kernel(float* __restrict__ out) {
    __shared__ uint2 sp[8][BUCKET_CAP];
    const int warp = threadIdx.x >> 5;
    const int lane = threadIdx.x & 31;
    const int node = blockIdx.x * 8 + warp;   // 6250 * 8 = 50000 exactly

    int cnt = g_count[node];
    if (cnt > BUCKET_CAP) cnt = BUCKET_CAP;

    const uint2* bkt = g_bucket + (size_t)node * BUCKET_CAP;
    for (int i = lane; i < cnt; i += 32) sp[warp][i] = bkt[i];
    __syncwarp();

    float acc[8];
    #pragma unroll
    for (int j = 0; j < 8; j++) acc[j] = 0.f;

    const int co = lane * 8;                  // fp16 feature offset for this lane (16 B)
    int i = 0;
    for (; i + 4 <= cnt; i += 4) {
        uint2 e0 = sp[warp][i + 0];
        uint2 e1 = sp[warp][i + 1];
        uint2 e2 = sp[warp][i + 2];
        uint2 e3 = sp[warp][i + 3];
        uint4 v0 = *(const uint4*)(g_y + (size_t)e0.x * DIM + co);
        uint4 v1 = *(const uint4*)(g_y + (size_t)e1.x * DIM + co);
        uint4 v2 = *(const uint4*)(g_y + (size_t)e2.x * DIM + co);
        uint4 v3 = *(const uint4*)(g_y + (size_t)e3.x * DIM + co);
        #pragma unroll
        for (int q = 0; q < 4; q++) {
            uint4 v = (q == 0) ? v0 : (q == 1) ? v1 : (q == 2) ? v2 : v3;
            float w = __uint_as_float((q == 0 ? e0 : q == 1 ? e1 : q == 2 ? e2 : e3).y);
            float2 f0 = __half22float2(*(__half2*)&v.x);
            float2 f1 = __half22float2(*(__half2*)&v.y);
            float2 f2 = __half22float2(*(__half2*)&v.z);
            float2 f3 = __half22float2(*(__half2*)&v.w);
            acc[0] = fmaf(w, f0.x, acc[0]); acc[1] = fmaf(w, f0.y, acc[1]);
            acc[2] = fmaf(w, f1.x, acc[2]); acc[3] = fmaf(w, f1.y, acc[3]);
            acc[4] = fmaf(w, f2.x, acc[4]); acc[5] = fmaf(w, f2.y, acc[5]);
            acc[6] = fmaf(w, f3.x, acc[6]); acc[7] = fmaf(w, f3.y, acc[7]);
        }
    }
    for (; i < cnt; i++) {
        uint2 e = sp[warp][i];
        float w = __uint_as_float(e.y);
        uint4 v = *(const uint4*)(g_y + (size_t)e.x * DIM + co);
        float2 f0 = __half22float2(*(__half2*)&v.x);
        float2 f1 = __half22float2(*(__half2*)&v.y);
        float2 f2 = __half22float2(*(__half2*)&v.z);
        float2 f3 = __half22float2(*(__half2*)&v.w);
        acc[0] = fmaf(w, f0.x, acc[0]); acc[1] = fmaf(w, f0.y, acc[1]);
        acc[2] = fmaf(w, f1.x, acc[2]); acc[3] = fmaf(w, f1.y, acc[3]);
        acc[4] = fmaf(w, f2.x, acc[4]); acc[5] = fmaf(w, f2.y, acc[5]);
        acc[6] = fmaf(w, f3.x, acc[6]); acc[7] = fmaf(w, f3.y, acc[7]);
    }

    float4 o0, o1;
    o0.x = fmaxf(acc[0], 0.f); o0.y = fmaxf(acc[1], 0.f);
    o0.z = fmaxf(acc[2], 0.f); o0.w = fmaxf(acc[3], 0.f);
    o1.x = fmaxf(acc[4], 0.f); o1.y = fmaxf(acc[5], 0.f);
    o1.z = fmaxf(acc[6], 0.f); o1.w = fmaxf(acc[7], 0.f);
    float* orow = out + (size_t)node * DIM + co;
    *(float4*)(orow + 0) = o0;
    *(float4*)(orow + 4) = o1;
}

// ---------------- host-side streams/events (created once, no device mem) ----------------
namespace {
struct LaunchCtx {
    cudaStream_t s1, s2;
    cudaEvent_t e0, e1, e2;
    void* count_ptr;
    LaunchCtx() {
        cudaStreamCreateWithFlags(&s1, cudaStreamNonBlocking);
        cudaStreamCreateWithFlags(&s2, cudaStreamNonBlocking);
        cudaEventCreateWithFlags(&e0, cudaEventDisableTiming);
        cudaEventCreateWithFlags(&e1, cudaEventDisableTiming);
        cudaEventCreateWithFlags(&e2, cudaEventDisableTiming);
        cudaGetSymbolAddress(&count_ptr, g_count);
        cudaFuncSetAttribute(gemm_kernel,
                             cudaFuncAttributeMaxDynamicSharedMemorySize, GEMM_SMEM);
    }
};
LaunchCtx g_ctx;
}

extern "C" void kernel_launch(void* const* d_in, const int* in_sizes, int n_in,
                              void* d_out, int out_size) {
    const float* x    = (const float*)d_in[0];   // [N_NODES, 256]
    const int*   erow = (const int*)  d_in[1];   // [E]
    const int*   ecol = (const int*)  d_in[2];   // [E]
    const float* ev   = (const float*)d_in[3];   // [E]
    const float* W    = (const float*)d_in[4];   // [256, 256]
    float* out = (float*)d_out;                  // [N_NODES, 256]

    // fork from the (capturing) default stream
    cudaEventRecord(g_ctx.e0, 0);
    cudaStreamWaitEvent(g_ctx.s1, g_ctx.e0, 0);
    cudaStreamWaitEvent(g_ctx.s2, g_ctx.e0, 0);

    // chain 2: GEMM (longer chain)
    conv_xw_kernel<<<(M_PAD * 64 + 255) / 256, 256, 0, g_ctx.s2>>>(x, W);
    gemm_kernel<<<NGEMM_BLKS, 256, GEMM_SMEM, g_ctx.s2>>>();

    // chain 1: scatter
    cudaMemsetAsync(g_ctx.count_ptr, 0, N_NODES * sizeof(int), g_ctx.s1);
    scatter_kernel<<<NSCAT_BLKS, 256, 0, g_ctx.s1>>>(erow, ecol, ev);

    // join
    cudaEventRecord(g_ctx.e1, g_ctx.s1);
    cudaEventRecord(g_ctx.e2, g_ctx.s2);
    cudaStreamWaitEvent(0, g_ctx.e1, 0);
    cudaStreamWaitEvent(0, g_ctx.e2, 0);

    aggregate_relu_kernel<<<N_NODES / 8, 256>>>(out);
}